// round 2
// baseline (speedup 1.0000x reference)
#include <cuda_runtime.h>
#include <cuda_bf16.h>
#include <math.h>
#include <stdint.h>

#define TOKENS 8192
#define DMODEL 1024
#define VOCAB  32000
#define NCHUNK 500   // 64-wide vocab chunks (32000/64)

// -------- device scratch (allocation-free contract: __device__ globals) -----
__device__ __align__(16) __nv_bfloat16 g_xb[TOKENS * DMODEL];   // 16 MB
__device__ __align__(16) __nv_bfloat16 g_wb[VOCAB * DMODEL];    // 64 MB
__device__ float g_pmax[NCHUNK * TOKENS];                       // 16 MB, chunk-major
__device__ float g_psum[NCHUNK * TOKENS];                       // 16 MB, chunk-major
__device__ float g_tscore[TOKENS];

// ---------------------------- fp32 -> bf16 convert --------------------------
__global__ void cvt_x_kernel(const float4* __restrict__ in, int n4) {
    uint2* out = reinterpret_cast<uint2*>(g_xb);
    int stride = gridDim.x * blockDim.x;
    for (int i = blockIdx.x * blockDim.x + threadIdx.x; i < n4; i += stride) {
        float4 v = in[i];
        __nv_bfloat162 a, b;
        a.x = __float2bfloat16(v.x); a.y = __float2bfloat16(v.y);
        b.x = __float2bfloat16(v.z); b.y = __float2bfloat16(v.w);
        uint2 o;
        o.x = *reinterpret_cast<unsigned int*>(&a);
        o.y = *reinterpret_cast<unsigned int*>(&b);
        out[i] = o;
    }
}

__global__ void cvt_w_kernel(const float4* __restrict__ in, int n4) {
    uint2* out = reinterpret_cast<uint2*>(g_wb);
    int stride = gridDim.x * blockDim.x;
    for (int i = blockIdx.x * blockDim.x + threadIdx.x; i < n4; i += stride) {
        float4 v = in[i];
        __nv_bfloat162 a, b;
        a.x = __float2bfloat16(v.x); a.y = __float2bfloat16(v.y);
        b.x = __float2bfloat16(v.z); b.y = __float2bfloat16(v.w);
        uint2 o;
        o.x = *reinterpret_cast<unsigned int*>(&a);
        o.y = *reinterpret_cast<unsigned int*>(&b);
        out[i] = o;
    }
}

// ------------------------------- mma helper ---------------------------------
__device__ __forceinline__ void mma16816(float* c, const uint32_t* a,
                                         uint32_t b0, uint32_t b1) {
    asm volatile(
        "mma.sync.aligned.m16n8k16.row.col.f32.bf16.bf16.f32 "
        "{%0,%1,%2,%3}, {%4,%5,%6,%7}, {%8,%9}, {%0,%1,%2,%3};\n"
        : "+f"(c[0]), "+f"(c[1]), "+f"(c[2]), "+f"(c[3])
        : "r"(a[0]), "r"(a[1]), "r"(a[2]), "r"(a[3]), "r"(b0), "r"(b1));
}

// -------------------- GEMM + flash partial (max, sumexp) --------------------
// CTA tile: 128 tokens x 128 vocab, K=1024 in chunks of 64.
// 8 warps as 4x2: warp tile 32 rows x 64 cols.
// Epilogue: per-token (max, sumexp) over the warp's 64 vocab cols -> one chunk.
__global__ __launch_bounds__(256) void gemm_partial_kernel() {
    __shared__ __nv_bfloat16 As[128][72];  // pad 8 -> row stride 36 words (conflict-free)
    __shared__ __nv_bfloat16 Bs[128][72];

    const int tid  = threadIdx.x;
    const int bx   = blockIdx.x;           // token tile (fast -> W reuse in L2)
    const int by   = blockIdx.y;           // vocab tile
    const int tok0 = bx * 128;
    const int n0g  = by * 128;
    const int wid  = tid >> 5, lane = tid & 31;
    const int wr   = wid >> 1, wc = wid & 1;
    const int g    = lane >> 2, tig = lane & 3;

    float acc[2][8][4];
#pragma unroll
    for (int mt = 0; mt < 2; mt++)
#pragma unroll
        for (int nt = 0; nt < 8; nt++)
#pragma unroll
            for (int i = 0; i < 4; i++) acc[mt][nt][i] = 0.f;

    for (int ko = 0; ko < DMODEL; ko += 64) {
#pragma unroll
        for (int j = 0; j < 4; j++) {
            int idx = tid + j * 256;           // 1024 uint4 per tile
            int row = idx >> 3, kb = idx & 7;
            *(uint4*)&As[row][kb * 8] =
                *(const uint4*)&g_xb[(size_t)(tok0 + row) * DMODEL + ko + kb * 8];
            *(uint4*)&Bs[row][kb * 8] =
                *(const uint4*)&g_wb[(size_t)(n0g + row) * DMODEL + ko + kb * 8];
        }
        __syncthreads();

#pragma unroll
        for (int ks = 0; ks < 4; ks++) {
            const int k0 = ks * 16;
            uint32_t af[2][4];
#pragma unroll
            for (int mt = 0; mt < 2; mt++) {
                int r0 = wr * 32 + mt * 16 + g;
                af[mt][0] = *(const uint32_t*)&As[r0][k0 + tig * 2];
                af[mt][1] = *(const uint32_t*)&As[r0 + 8][k0 + tig * 2];
                af[mt][2] = *(const uint32_t*)&As[r0][k0 + 8 + tig * 2];
                af[mt][3] = *(const uint32_t*)&As[r0 + 8][k0 + 8 + tig * 2];
            }
#pragma unroll
            for (int nt = 0; nt < 8; nt++) {
                int nrow = wc * 64 + nt * 8 + g;
                uint32_t b0 = *(const uint32_t*)&Bs[nrow][k0 + tig * 2];
                uint32_t b1 = *(const uint32_t*)&Bs[nrow][k0 + 8 + tig * 2];
                mma16816(acc[0][nt], af[0], b0, b1);
                mma16816(acc[1][nt], af[1], b0, b1);
            }
        }
        __syncthreads();
    }

    // Epilogue: per-row max + sumexp over this warp's 64 vocab cols.
    // Row r of an mma tile is held by the 4 lanes with the same g (tig 0..3).
    const int chunk = by * 2 + wc;
#pragma unroll
    for (int mt = 0; mt < 2; mt++) {
        float mA = -1e30f, mB = -1e30f;
#pragma unroll
        for (int nt = 0; nt < 8; nt++) {
            mA = fmaxf(mA, fmaxf(acc[mt][nt][0], acc[mt][nt][1]));  // row g
            mB = fmaxf(mB, fmaxf(acc[mt][nt][2], acc[mt][nt][3]));  // row g+8
        }
        mA = fmaxf(mA, __shfl_xor_sync(0xffffffffu, mA, 1));
        mA = fmaxf(mA, __shfl_xor_sync(0xffffffffu, mA, 2));
        mB = fmaxf(mB, __shfl_xor_sync(0xffffffffu, mB, 1));
        mB = fmaxf(mB, __shfl_xor_sync(0xffffffffu, mB, 2));

        float sA = 0.f, sB = 0.f;
#pragma unroll
        for (int nt = 0; nt < 8; nt++) {
            sA += __expf(acc[mt][nt][0] - mA) + __expf(acc[mt][nt][1] - mA);
            sB += __expf(acc[mt][nt][2] - mB) + __expf(acc[mt][nt][3] - mB);
        }
        sA += __shfl_xor_sync(0xffffffffu, sA, 1);
        sA += __shfl_xor_sync(0xffffffffu, sA, 2);
        sB += __shfl_xor_sync(0xffffffffu, sB, 1);
        sB += __shfl_xor_sync(0xffffffffu, sB, 2);

        if (tig == 0) {
            int tA = tok0 + wr * 32 + mt * 16 + g;
            g_pmax[chunk * TOKENS + tA] = mA;
            g_psum[chunk * TOKENS + tA] = sA;
            g_pmax[chunk * TOKENS + tA + 8] = mB;
            g_psum[chunk * TOKENS + tA + 8] = sB;
        }
    }
}

// ----------------------- target score: x_t . W[target_t] --------------------
__global__ __launch_bounds__(256) void tscore_kernel(const float* __restrict__ x,
                                                     const float* __restrict__ w,
                                                     const int* __restrict__ target) {
    int wid = threadIdx.x >> 5, lane = threadIdx.x & 31;
    int t = blockIdx.x * 8 + wid;
    int tgt = target[t];
    const float4* xr = reinterpret_cast<const float4*>(x + (size_t)t * DMODEL);
    const float4* wrow = reinterpret_cast<const float4*>(w + (size_t)tgt * DMODEL);
    float s = 0.f;
#pragma unroll
    for (int i = 0; i < 8; i++) {
        float4 a = xr[lane + i * 32];
        float4 b = wrow[lane + i * 32];
        s += a.x * b.x + a.y * b.y + a.z * b.z + a.w * b.w;
    }
#pragma unroll
    for (int o = 16; o; o >>= 1) s += __shfl_xor_sync(0xffffffffu, s, o);
    if (lane == 0) g_tscore[t] = s;
}

// ------------------------------ final reduction -----------------------------
__global__ void final_kernel(float* __restrict__ out) {
    __shared__ double sred[1024];
    const int tid = threadIdx.x;
    double local = 0.0;
    for (int t = tid; t < TOKENS; t += 1024) {
        float gm = -1e30f;
        for (int c = 0; c < NCHUNK; c++)
            gm = fmaxf(gm, g_pmax[c * TOKENS + t]);
        float s = 0.f;
        for (int c = 0; c < NCHUNK; c++)
            s += g_psum[c * TOKENS + t] * __expf(g_pmax[c * TOKENS + t] - gm);
        local += (double)(logf(s) + gm - g_tscore[t]);
    }
    sred[tid] = local;
    __syncthreads();
    for (int o = 512; o; o >>= 1) {
        if (tid < o) sred[tid] += sred[tid + o];
        __syncthreads();
    }
    if (tid == 0) out[0] = (float)sred[0];
}

// --------------------------------- launch -----------------------------------
extern "C" void kernel_launch(void* const* d_in, const int* in_sizes, int n_in,
                              void* d_out, int out_size) {
    const float* x = (const float*)d_in[0];
    const float* w = (const float*)d_in[1];
    const int* target = (const int*)d_in[2];
    float* out = (float*)d_out;

    (void)in_sizes; (void)n_in; (void)out_size;

    cvt_x_kernel<<<2048, 256>>>((const float4*)x, TOKENS * DMODEL / 4);
    cvt_w_kernel<<<4096, 256>>>((const float4*)w, VOCAB * DMODEL / 4);

    dim3 grid(TOKENS / 128, VOCAB / 128);  // (64, 250), token-tile fast
    gemm_partial_kernel<<<grid, 256>>>();

    tscore_kernel<<<TOKENS / 8, 256>>>(x, w, target);

    final_kernel<<<1, 1024>>>(out);
}

// round 4
// speedup vs baseline: 2.7691x; 2.7691x over previous
#include <cuda_runtime.h>
#include <cuda_bf16.h>
#include <math.h>
#include <stdint.h>

#define TOKENS 8192
#define DMODEL 1024
#define VOCAB  32000
#define TILE_M 128
#define TILE_N 256
#define NCHUNK_TC (VOCAB / TILE_N)   // 125
#define NCHUNK_FB (VOCAB / 64)       // 500
#define KCHUNK 64
#define NKSTAGE (DMODEL / KCHUNK)    // 16
#define DEPTH 3
#define STAGE_BYTES 49152            // A 16KB + B 32KB
#define B_OFF 16384

// idesc kind::f16: dtype F32(1<<4), atype BF16(1<<7), btype BF16(1<<10),
// N/8 << 17, M/16 << 24  ->  M=128, N=256
#define MMA_IDESC 0x08400490u

#if defined(__CUDA_ARCH_FEAT_SM103_ALL) || defined(__CUDA_ARCH_FEAT_SM100_ALL)
#define HAS_TCGEN05 1
#else
#define HAS_TCGEN05 0
#endif

// -------- device scratch (allocation-free contract) -------------------------
__device__ __align__(16) __nv_bfloat16 g_xb[TOKENS * DMODEL];   // 16 MB
__device__ __align__(16) __nv_bfloat16 g_wb[VOCAB * DMODEL];    // 64 MB
__device__ float g_pmax[NCHUNK_FB * TOKENS];                    // sized for max
__device__ float g_psum[NCHUNK_FB * TOKENS];
__device__ float g_tscore[TOKENS];
__device__ int   g_use_tc;

// ----------------------------- arch dispatch flag ---------------------------
__global__ void flag_kernel() {
#if HAS_TCGEN05
    g_use_tc = 1;
#else
    g_use_tc = 0;
#endif
}

// ---------------------------- fp32 -> bf16 convert --------------------------
__global__ void cvt_kernel(const float4* __restrict__ in,
                           __nv_bfloat16* __restrict__ outp, int n4) {
    uint2* out = reinterpret_cast<uint2*>(outp);
    int stride = gridDim.x * blockDim.x;
    for (int i = blockIdx.x * blockDim.x + threadIdx.x; i < n4; i += stride) {
        float4 v = in[i];
        __nv_bfloat162 a, b;
        a.x = __float2bfloat16(v.x); a.y = __float2bfloat16(v.y);
        b.x = __float2bfloat16(v.z); b.y = __float2bfloat16(v.w);
        uint2 o;
        o.x = *reinterpret_cast<unsigned int*>(&a);
        o.y = *reinterpret_cast<unsigned int*>(&b);
        out[i] = o;
    }
}

// ======================= tcgen05 path (feature-gated) =======================
#if HAS_TCGEN05
__device__ __forceinline__ uint32_t smem_u32(const void* p) {
    uint32_t a;
    asm("{ .reg .u64 t; cvta.to.shared.u64 t, %1; cvt.u32.u64 %0, t; }"
        : "=r"(a) : "l"(p));
    return a;
}
#define SW128(off) ((off) ^ (((off) >> 3) & 0x70))

static __device__ __forceinline__ uint64_t make_desc(uint32_t base) {
    // SW128 K-major: layout=2, version=1, SBO=64, LBO=1
    uint64_t d = ((uint64_t)2 << 61) | ((uint64_t)1 << 46) |
                 ((uint64_t)64 << 32) | ((uint64_t)1 << 16);
    return d | ((uint64_t)(base >> 4) & 0x3FFF);
}

__device__ __forceinline__ void mma_f16_ss_cg1(uint32_t d, uint64_t ad,
                                               uint64_t bd, uint32_t idesc,
                                               uint32_t en) {
    asm volatile(
        "{\n\t.reg .pred p;\n\t"
        "setp.ne.u32 p, %5, 0;\n\t"
        "tcgen05.mma.cta_group::1.kind::f16 [%0], %1, %2, %3, {%4,%4,%4,%4}, p;\n\t}"
        :: "r"(d), "l"(ad), "l"(bd), "r"(idesc), "r"(0u), "r"(en) : "memory");
}

#define MBAR_INIT(a, c) \
    asm volatile("mbarrier.init.shared.b64 [%0], %1;" :: "r"(a), "r"(c) : "memory")
#define TC_COMMIT(a) \
    asm volatile("tcgen05.commit.cta_group::1.mbarrier::arrive::one.shared::cluster.b64 [%0];" \
                 :: "r"(a) : "memory")
#define TC_FENCE_AFTER() asm volatile("tcgen05.fence::after_thread_sync;" ::: "memory")
#define FENCE_ASYNC() asm volatile("fence.proxy.async.shared::cta;" ::: "memory")
#define CP_COMMIT() asm volatile("cp.async.commit_group;" ::: "memory")
#define CP_WAIT2() asm volatile("cp.async.wait_group 2;" ::: "memory")

#define MBAR_WAIT(mbar, parity) do {                                          \
    uint32_t _m = (mbar); uint32_t _p = (parity); uint32_t _d;                \
    asm volatile("{\n\t.reg .pred p;\n\t"                                     \
        "mbarrier.try_wait.parity.acquire.cta.shared::cta.b64 p, [%1], %2;\n\t" \
        "selp.b32 %0, 1, 0, p;\n\t}"                                          \
        : "=r"(_d) : "r"(_m), "r"(_p) : "memory");                            \
    if (!_d) {                                                                \
        asm volatile("{\n\t.reg .pred P1;\n\t"                                \
            "W%=:\n\t"                                                        \
            "mbarrier.try_wait.parity.acquire.cta.shared::cta.b64 P1, [%0], %1, 0x989680;\n\t" \
            "@P1 bra.uni D%=;\n\t"                                            \
            "bra.uni W%=;\n\t"                                                \
            "D%=:\n\t}" :: "r"(_m), "r"(_p) : "memory");                      \
    }                                                                         \
} while (0)

#define TC_LD_X32(r, addr)                                                    \
    asm volatile("tcgen05.ld.sync.aligned.32x32b.x32.b32 "                    \
        "{%0,%1,%2,%3,%4,%5,%6,%7,%8,%9,%10,%11,%12,%13,%14,%15,"             \
        "%16,%17,%18,%19,%20,%21,%22,%23,%24,%25,%26,%27,%28,%29,%30,%31}, [%32];" \
        : "=r"((r)[0]), "=r"((r)[1]), "=r"((r)[2]), "=r"((r)[3]),             \
          "=r"((r)[4]), "=r"((r)[5]), "=r"((r)[6]), "=r"((r)[7]),             \
          "=r"((r)[8]), "=r"((r)[9]), "=r"((r)[10]), "=r"((r)[11]),           \
          "=r"((r)[12]), "=r"((r)[13]), "=r"((r)[14]), "=r"((r)[15]),         \
          "=r"((r)[16]), "=r"((r)[17]), "=r"((r)[18]), "=r"((r)[19]),         \
          "=r"((r)[20]), "=r"((r)[21]), "=r"((r)[22]), "=r"((r)[23]),         \
          "=r"((r)[24]), "=r"((r)[25]), "=r"((r)[26]), "=r"((r)[27]),         \
          "=r"((r)[28]), "=r"((r)[29]), "=r"((r)[30]), "=r"((r)[31])          \
        : "r"(addr))
#define TC_WAIT_LD() asm volatile("tcgen05.wait::ld.sync.aligned;" ::: "memory")

__device__ __forceinline__ void load_stage(uint32_t data_base, int slot,
                                           int stage, int tok0, int n0, int tid) {
    const int ko = stage * KCHUNK;
    const uint32_t sbase = data_base + (uint32_t)slot * STAGE_BYTES;
#pragma unroll
    for (int j = 0; j < 12; j++) {
        int c = tid + j * 256;               // 0..3071 16B chunks
        int isB = c >= 1024;
        int cc = isB ? c - 1024 : c;
        int row = cc >> 3, c16 = cc & 7;
        uint32_t boff = (uint32_t)(row * 128 + c16 * 16);
        uint32_t dst = sbase + (isB ? (uint32_t)B_OFF : 0u) + SW128(boff);
        const __nv_bfloat16* src =
            isB ? &g_wb[(size_t)(n0 + row) * DMODEL + ko + c16 * 8]
                : &g_xb[(size_t)(tok0 + row) * DMODEL + ko + c16 * 8];
        asm volatile("cp.async.cg.shared.global [%0], [%1], 16;"
                     :: "r"(dst), "l"(src) : "memory");
    }
}
#endif  // HAS_TCGEN05

__global__ __launch_bounds__(256, 1) void gemm_tc_kernel() {
#if HAS_TCGEN05
    extern __shared__ char smem[];
    const uint32_t raw = smem_u32(smem);
    const uint32_t data_base = (raw + 1023u) & ~1023u;
    const uint32_t hdr = data_base + DEPTH * STAGE_BYTES;  // tmem ptr + barriers
    char* comb_c = smem + (data_base - raw);

    const int tid = threadIdx.x;
    const int wid = tid >> 5, lane = tid & 31;
    const int tok0 = blockIdx.x * TILE_M;
    const int n0 = blockIdx.y * TILE_N;

    if (tid == 0) {
        MBAR_INIT(hdr + 8, 1u);
        MBAR_INIT(hdr + 16, 1u);
        MBAR_INIT(hdr + 24, 1u);
        MBAR_INIT(hdr + 32, 1u);   // done barrier
    }
    if (wid == 4) {
        asm volatile("tcgen05.alloc.cta_group::1.sync.aligned.shared::cta.b32 [%0], %1;"
                     :: "r"(hdr), "r"(256u) : "memory");
        asm volatile("tcgen05.relinquish_alloc_permit.cta_group::1.sync.aligned;");
    }
    __syncthreads();
    uint32_t tmem;
    asm volatile("ld.shared.b32 %0, [%1];" : "=r"(tmem) : "r"(hdr));

#pragma unroll
    for (int s = 0; s < DEPTH; s++) {
        load_stage(data_base, s, s, tok0, n0, tid);
        CP_COMMIT();
    }

    for (int ks = 0; ks < NKSTAGE; ks++) {
        const int slot = ks % DEPTH;
        CP_WAIT2();
        FENCE_ASYNC();
        __syncthreads();
        if (tid == 128) {
            uint64_t ad = make_desc(data_base + (uint32_t)slot * STAGE_BYTES);
            uint64_t bd = make_desc(data_base + (uint32_t)slot * STAGE_BYTES + B_OFF);
#pragma unroll
            for (int kk = 0; kk < 4; kk++)
                mma_f16_ss_cg1(tmem, ad + kk * 2, bd + kk * 2, MMA_IDESC,
                               (uint32_t)(ks | kk));
            TC_COMMIT(hdr + 8 + slot * 8);
        }
        const int ps = ks + DEPTH;
        if (ps < NKSTAGE) {
            MBAR_WAIT(hdr + 8 + slot * 8, (uint32_t)((ks / DEPTH) & 1));
            load_stage(data_base, slot, ps, tok0, n0, tid);
        }
        CP_COMMIT();  // one group per iteration keeps wait_group<2> exact
    }

    if (tid == 128) TC_COMMIT(hdr + 32);
    MBAR_WAIT(hdr + 32, 0u);
    TC_FENCE_AFTER();

    // epilogue: warp w reads rows (w&3)*32+lane, cols (w>>2)*128 .. +127
    const int half = wid >> 2;
    const int mrow = (wid & 3) * 32 + lane;
    float runm = -1e30f, runs = 0.f;
#pragma unroll
    for (int cb = 0; cb < 4; cb++) {
        uint32_t r[32];
        TC_LD_X32(r, tmem + (uint32_t)(half * 128 + cb * 32));
        TC_WAIT_LD();
        float bm = -1e30f;
#pragma unroll
        for (int i = 0; i < 32; i++) bm = fmaxf(bm, __uint_as_float(r[i]));
        float nm = fmaxf(runm, bm);
        float sc = __expf(runm - nm);
        float bs = 0.f;
#pragma unroll
        for (int i = 0; i < 32; i++) bs += __expf(__uint_as_float(r[i]) - nm);
        runs = runs * sc + bs;
        runm = nm;
    }

    __syncthreads();  // MMAs + loads done; reuse stage smem for combine
    float* comb = reinterpret_cast<float*>(comb_c);
    comb[half * 128 + mrow] = runm;            // max[2][128]
    comb[256 + half * 128 + mrow] = runs;      // sum[2][128]
    __syncthreads();
    if (tid < 128) {
        float m0 = comb[tid], m1 = comb[128 + tid];
        float s0 = comb[256 + tid], s1 = comb[384 + tid];
        float m = fmaxf(m0, m1);
        float s = s0 * __expf(m0 - m) + s1 * __expf(m1 - m);
        g_pmax[blockIdx.y * TOKENS + tok0 + tid] = m;
        g_psum[blockIdx.y * TOKENS + tok0 + tid] = s;
    }
    __syncthreads();
    if (wid == 4) {
        asm volatile("tcgen05.dealloc.cta_group::1.sync.aligned.b32 %0, %1;"
                     :: "r"(tmem), "r"(256u));
    }
#endif  // HAS_TCGEN05
}

// =================== fallback path: mma.sync (always built) =================
__device__ __forceinline__ void mma16816(float* c, const uint32_t* a,
                                         uint32_t b0, uint32_t b1) {
    asm volatile(
        "mma.sync.aligned.m16n8k16.row.col.f32.bf16.bf16.f32 "
        "{%0,%1,%2,%3}, {%4,%5,%6,%7}, {%8,%9}, {%0,%1,%2,%3};\n"
        : "+f"(c[0]), "+f"(c[1]), "+f"(c[2]), "+f"(c[3])
        : "r"(a[0]), "r"(a[1]), "r"(a[2]), "r"(a[3]), "r"(b0), "r"(b1));
}

__global__ __launch_bounds__(256) void gemm_fb_kernel() {
    if (g_use_tc) return;
    __shared__ __nv_bfloat16 As[128][72];
    __shared__ __nv_bfloat16 Bs[128][72];

    const int tid  = threadIdx.x;
    const int tok0 = blockIdx.x * 128;
    const int n0g  = blockIdx.y * 128;
    const int wid  = tid >> 5, lane = tid & 31;
    const int wr   = wid >> 1, wc = wid & 1;
    const int g    = lane >> 2, tig = lane & 3;

    float acc[2][8][4];
#pragma unroll
    for (int mt = 0; mt < 2; mt++)
#pragma unroll
        for (int nt = 0; nt < 8; nt++)
#pragma unroll
            for (int i = 0; i < 4; i++) acc[mt][nt][i] = 0.f;

    for (int ko = 0; ko < DMODEL; ko += 64) {
#pragma unroll
        for (int j = 0; j < 4; j++) {
            int idx = tid + j * 256;
            int row = idx >> 3, kb = idx & 7;
            *(uint4*)&As[row][kb * 8] =
                *(const uint4*)&g_xb[(size_t)(tok0 + row) * DMODEL + ko + kb * 8];
            *(uint4*)&Bs[row][kb * 8] =
                *(const uint4*)&g_wb[(size_t)(n0g + row) * DMODEL + ko + kb * 8];
        }
        __syncthreads();
#pragma unroll
        for (int ks = 0; ks < 4; ks++) {
            const int k0 = ks * 16;
            uint32_t af[2][4];
#pragma unroll
            for (int mt = 0; mt < 2; mt++) {
                int r0 = wr * 32 + mt * 16 + g;
                af[mt][0] = *(const uint32_t*)&As[r0][k0 + tig * 2];
                af[mt][1] = *(const uint32_t*)&As[r0 + 8][k0 + tig * 2];
                af[mt][2] = *(const uint32_t*)&As[r0][k0 + 8 + tig * 2];
                af[mt][3] = *(const uint32_t*)&As[r0 + 8][k0 + 8 + tig * 2];
            }
#pragma unroll
            for (int nt = 0; nt < 8; nt++) {
                int nrow = wc * 64 + nt * 8 + g;
                uint32_t b0 = *(const uint32_t*)&Bs[nrow][k0 + tig * 2];
                uint32_t b1 = *(const uint32_t*)&Bs[nrow][k0 + 8 + tig * 2];
                mma16816(acc[0][nt], af[0], b0, b1);
                mma16816(acc[1][nt], af[1], b0, b1);
            }
        }
        __syncthreads();
    }

    const int chunk = blockIdx.y * 2 + wc;
#pragma unroll
    for (int mt = 0; mt < 2; mt++) {
        float mA = -1e30f, mB = -1e30f;
#pragma unroll
        for (int nt = 0; nt < 8; nt++) {
            mA = fmaxf(mA, fmaxf(acc[mt][nt][0], acc[mt][nt][1]));
            mB = fmaxf(mB, fmaxf(acc[mt][nt][2], acc[mt][nt][3]));
        }
        mA = fmaxf(mA, __shfl_xor_sync(0xffffffffu, mA, 1));
        mA = fmaxf(mA, __shfl_xor_sync(0xffffffffu, mA, 2));
        mB = fmaxf(mB, __shfl_xor_sync(0xffffffffu, mB, 1));
        mB = fmaxf(mB, __shfl_xor_sync(0xffffffffu, mB, 2));
        float sA = 0.f, sB = 0.f;
#pragma unroll
        for (int nt = 0; nt < 8; nt++) {
            sA += __expf(acc[mt][nt][0] - mA) + __expf(acc[mt][nt][1] - mA);
            sB += __expf(acc[mt][nt][2] - mB) + __expf(acc[mt][nt][3] - mB);
        }
        sA += __shfl_xor_sync(0xffffffffu, sA, 1);
        sA += __shfl_xor_sync(0xffffffffu, sA, 2);
        sB += __shfl_xor_sync(0xffffffffu, sB, 1);
        sB += __shfl_xor_sync(0xffffffffu, sB, 2);
        if (tig == 0) {
            int tA = tok0 + wr * 32 + mt * 16 + g;
            g_pmax[chunk * TOKENS + tA] = mA;
            g_psum[chunk * TOKENS + tA] = sA;
            g_pmax[chunk * TOKENS + tA + 8] = mB;
            g_psum[chunk * TOKENS + tA + 8] = sB;
        }
    }
}

// ----------------------- target score: x_t . W[target_t] --------------------
__global__ __launch_bounds__(256) void tscore_kernel(const float* __restrict__ x,
                                                     const float* __restrict__ w,
                                                     const int* __restrict__ target) {
    int wid = threadIdx.x >> 5, lane = threadIdx.x & 31;
    int t = blockIdx.x * 8 + wid;
    int tgt = target[t];
    const float4* xr = reinterpret_cast<const float4*>(x + (size_t)t * DMODEL);
    const float4* wrow = reinterpret_cast<const float4*>(w + (size_t)tgt * DMODEL);
    float s = 0.f;
#pragma unroll
    for (int i = 0; i < 8; i++) {
        float4 a = xr[lane + i * 32];
        float4 b = wrow[lane + i * 32];
        s += a.x * b.x + a.y * b.y + a.z * b.z + a.w * b.w;
    }
#pragma unroll
    for (int o = 16; o; o >>= 1) s += __shfl_xor_sync(0xffffffffu, s, o);
    if (lane == 0) g_tscore[t] = s;
}

// ------------------------------ final reduction -----------------------------
__global__ void final_kernel(float* __restrict__ out) {
    __shared__ double sred[1024];
    const int tid = threadIdx.x;
    const int nch = g_use_tc ? NCHUNK_TC : NCHUNK_FB;
    double local = 0.0;
    for (int t = tid; t < TOKENS; t += 1024) {
        float gm = -1e30f;
        for (int c = 0; c < nch; c++)
            gm = fmaxf(gm, g_pmax[c * TOKENS + t]);
        float s = 0.f;
        for (int c = 0; c < nch; c++)
            s += g_psum[c * TOKENS + t] * __expf(g_pmax[c * TOKENS + t] - gm);
        local += (double)(logf(s) + gm - g_tscore[t]);
    }
    sred[tid] = local;
    __syncthreads();
    for (int o = 512; o; o >>= 1) {
        if (tid < o) sred[tid] += sred[tid + o];
        __syncthreads();
    }
    if (tid == 0) out[0] = (float)sred[0];
}

// --------------------------------- launch -----------------------------------
extern "C" void kernel_launch(void* const* d_in, const int* in_sizes, int n_in,
                              void* d_out, int out_size) {
    const float* x = (const float*)d_in[0];
    const float* w = (const float*)d_in[1];
    const int* target = (const int*)d_in[2];
    float* out = (float*)d_out;
    (void)in_sizes; (void)n_in; (void)out_size;

    const int smem_bytes = DEPTH * STAGE_BYTES + 2048;
    cudaFuncSetAttribute(gemm_tc_kernel,
                         cudaFuncAttributeMaxDynamicSharedMemorySize, smem_bytes);

    __nv_bfloat16* xb;  cudaGetSymbolAddress((void**)&xb, g_xb);
    __nv_bfloat16* wb;  cudaGetSymbolAddress((void**)&wb, g_wb);

    flag_kernel<<<1, 1>>>();
    cvt_kernel<<<2048, 256>>>((const float4*)x, xb, TOKENS * DMODEL / 4);
    cvt_kernel<<<4096, 256>>>((const float4*)w, wb, VOCAB * DMODEL / 4);

    dim3 grid_tc(TOKENS / TILE_M, VOCAB / TILE_N);  // (64, 125)
    gemm_tc_kernel<<<grid_tc, 256, smem_bytes>>>();

    dim3 grid_fb(TOKENS / 128, VOCAB / 128);        // (64, 250)
    gemm_fb_kernel<<<grid_fb, 256>>>();

    tscore_kernel<<<TOKENS / 8, 256>>>(x, w, target);
    final_kernel<<<1, 1024>>>(out);
}

// round 6
// speedup vs baseline: 4.7087x; 1.7005x over previous
#include <cuda_runtime.h>
#include <cuda_bf16.h>
#include <math.h>
#include <stdint.h>

#define TOKENS 8192
#define DMODEL 1024
#define VOCAB  32000
#define TILE_M 128
#define TILE_N 256
#define NCHUNK_TC (VOCAB / TILE_N)   // 125
#define NCHUNK_FB (VOCAB / 64)       // 500
#define KCHUNK 64
#define NKSTAGE (DMODEL / KCHUNK)    // 16
#define DEPTH 4
#define STAGE_BYTES 49152            // A 16KB + B 32KB
#define B_OFF 16384

// idesc kind::f16: dtype F32(1<<4), atype BF16(1<<7), btype BF16(1<<10),
// N/8 << 17, M/16 << 24  ->  M=128, N=256
#define MMA_IDESC 0x08400490u

#if defined(__CUDA_ARCH_FEAT_SM103_ALL) || defined(__CUDA_ARCH_FEAT_SM100_ALL)
#define HAS_TCGEN05 1
#else
#define HAS_TCGEN05 0
#endif

// -------- device scratch (allocation-free contract) -------------------------
__device__ __align__(16) __nv_bfloat16 g_xb[TOKENS * DMODEL];   // 16 MB
__device__ __align__(16) __nv_bfloat16 g_wb[VOCAB * DMODEL];    // 64 MB
__device__ float g_pmax[NCHUNK_FB * TOKENS];                    // sized for max
__device__ float g_psum[NCHUNK_FB * TOKENS];
__device__ float g_tscore[TOKENS];
__device__ float g_loss[TOKENS];
__device__ int   g_use_tc;

// ----------------------------- arch dispatch flag ---------------------------
__global__ void flag_kernel() {
#if HAS_TCGEN05
    g_use_tc = 1;
#else
    g_use_tc = 0;
#endif
}

// ---------------------------- fp32 -> bf16 convert --------------------------
__global__ void cvt_kernel(const float4* __restrict__ in,
                           __nv_bfloat16* __restrict__ outp, int n4) {
    uint2* out = reinterpret_cast<uint2*>(outp);
    int stride = gridDim.x * blockDim.x;
    for (int i = blockIdx.x * blockDim.x + threadIdx.x; i < n4; i += stride) {
        float4 v = in[i];
        __nv_bfloat162 a, b;
        a.x = __float2bfloat16(v.x); a.y = __float2bfloat16(v.y);
        b.x = __float2bfloat16(v.z); b.y = __float2bfloat16(v.w);
        uint2 o;
        o.x = *reinterpret_cast<unsigned int*>(&a);
        o.y = *reinterpret_cast<unsigned int*>(&b);
        out[i] = o;
    }
}

// ======================= tcgen05 path (feature-gated) =======================
#if HAS_TCGEN05
__device__ __forceinline__ uint32_t smem_u32(const void* p) {
    uint32_t a;
    asm("{ .reg .u64 t; cvta.to.shared.u64 t, %1; cvt.u32.u64 %0, t; }"
        : "=r"(a) : "l"(p));
    return a;
}
#define SW128(off) ((off) ^ (((off) >> 3) & 0x70))

static __device__ __forceinline__ uint64_t make_desc(uint32_t base) {
    // SW128 K-major: layout=2, version=1, SBO=64, LBO=1
    uint64_t d = ((uint64_t)2 << 61) | ((uint64_t)1 << 46) |
                 ((uint64_t)64 << 32) | ((uint64_t)1 << 16);
    return d | ((uint64_t)(base >> 4) & 0x3FFF);
}

__device__ __forceinline__ void mma_f16_ss_cg1(uint32_t d, uint64_t ad,
                                               uint64_t bd, uint32_t idesc,
                                               uint32_t en) {
    asm volatile(
        "{\n\t.reg .pred p;\n\t"
        "setp.ne.u32 p, %5, 0;\n\t"
        "tcgen05.mma.cta_group::1.kind::f16 [%0], %1, %2, %3, {%4,%4,%4,%4}, p;\n\t}"
        :: "r"(d), "l"(ad), "l"(bd), "r"(idesc), "r"(0u), "r"(en) : "memory");
}

#define MBAR_INIT(a, c) \
    asm volatile("mbarrier.init.shared.b64 [%0], %1;" :: "r"(a), "r"(c) : "memory")
#define TC_COMMIT(a) \
    asm volatile("tcgen05.commit.cta_group::1.mbarrier::arrive::one.shared::cluster.b64 [%0];" \
                 :: "r"(a) : "memory")
#define TC_FENCE_AFTER() asm volatile("tcgen05.fence::after_thread_sync;" ::: "memory")
#define FENCE_ASYNC() asm volatile("fence.proxy.async.shared::cta;" ::: "memory")
#define CP_COMMIT() asm volatile("cp.async.commit_group;" ::: "memory")
#define CP_WAIT2() asm volatile("cp.async.wait_group 2;" ::: "memory")

#define MBAR_WAIT(mbar, parity) do {                                          \
    uint32_t _m = (mbar); uint32_t _p = (parity); uint32_t _d;                \
    asm volatile("{\n\t.reg .pred p;\n\t"                                     \
        "mbarrier.try_wait.parity.acquire.cta.shared::cta.b64 p, [%1], %2;\n\t" \
        "selp.b32 %0, 1, 0, p;\n\t}"                                          \
        : "=r"(_d) : "r"(_m), "r"(_p) : "memory");                            \
    if (!_d) {                                                                \
        asm volatile("{\n\t.reg .pred P1;\n\t"                                \
            "W%=:\n\t"                                                        \
            "mbarrier.try_wait.parity.acquire.cta.shared::cta.b64 P1, [%0], %1, 0x989680;\n\t" \
            "@P1 bra.uni D%=;\n\t"                                            \
            "bra.uni W%=;\n\t"                                                \
            "D%=:\n\t}" :: "r"(_m), "r"(_p) : "memory");                      \
    }                                                                         \
} while (0)

#define TC_LD_X32(r, addr)                                                    \
    asm volatile("tcgen05.ld.sync.aligned.32x32b.x32.b32 "                    \
        "{%0,%1,%2,%3,%4,%5,%6,%7,%8,%9,%10,%11,%12,%13,%14,%15,"             \
        "%16,%17,%18,%19,%20,%21,%22,%23,%24,%25,%26,%27,%28,%29,%30,%31}, [%32];" \
        : "=r"((r)[0]), "=r"((r)[1]), "=r"((r)[2]), "=r"((r)[3]),             \
          "=r"((r)[4]), "=r"((r)[5]), "=r"((r)[6]), "=r"((r)[7]),             \
          "=r"((r)[8]), "=r"((r)[9]), "=r"((r)[10]), "=r"((r)[11]),           \
          "=r"((r)[12]), "=r"((r)[13]), "=r"((r)[14]), "=r"((r)[15]),         \
          "=r"((r)[16]), "=r"((r)[17]), "=r"((r)[18]), "=r"((r)[19]),         \
          "=r"((r)[20]), "=r"((r)[21]), "=r"((r)[22]), "=r"((r)[23]),         \
          "=r"((r)[24]), "=r"((r)[25]), "=r"((r)[26]), "=r"((r)[27]),         \
          "=r"((r)[28]), "=r"((r)[29]), "=r"((r)[30]), "=r"((r)[31])          \
        : "r"(addr))
#define TC_WAIT_LD() asm volatile("tcgen05.wait::ld.sync.aligned;" ::: "memory")

__device__ __forceinline__ void load_stage(uint32_t data_base, int slot,
                                           int stage, int tok0, int n0, int tid) {
    const int ko = stage * KCHUNK;
    const uint32_t sbase = data_base + (uint32_t)slot * STAGE_BYTES;
#pragma unroll
    for (int j = 0; j < 12; j++) {
        int c = tid + j * 256;               // 0..3071 16B chunks
        int isB = c >= 1024;
        int cc = isB ? c - 1024 : c;
        int row = cc >> 3, c16 = cc & 7;
        uint32_t boff = (uint32_t)(row * 128 + c16 * 16);
        uint32_t dst = sbase + (isB ? (uint32_t)B_OFF : 0u) + SW128(boff);
        const __nv_bfloat16* src =
            isB ? &g_wb[(size_t)(n0 + row) * DMODEL + ko + c16 * 8]
                : &g_xb[(size_t)(tok0 + row) * DMODEL + ko + c16 * 8];
        asm volatile("cp.async.cg.shared.global [%0], [%1], 16;"
                     :: "r"(dst), "l"(src) : "memory");
    }
}
#endif  // HAS_TCGEN05

__global__ __launch_bounds__(256, 1) void gemm_tc_kernel() {
#if HAS_TCGEN05
    extern __shared__ char smem[];
    const uint32_t raw = smem_u32(smem);
    const uint32_t data_base = (raw + 1023u) & ~1023u;
    const uint32_t hdr = data_base + DEPTH * STAGE_BYTES;  // tmem ptr + barriers
    char* comb_c = smem + (data_base - raw);

    const int tid = threadIdx.x;
    const int wid = tid >> 5, lane = tid & 31;
    const int tok0 = blockIdx.x * TILE_M;
    const int n0 = blockIdx.y * TILE_N;

    if (tid == 0) {
#pragma unroll
        for (int b = 0; b < DEPTH; b++) MBAR_INIT(hdr + 8 + b * 8, 1u);
        MBAR_INIT(hdr + 8 + DEPTH * 8, 1u);   // done barrier
    }
    if (wid == 4) {
        asm volatile("tcgen05.alloc.cta_group::1.sync.aligned.shared::cta.b32 [%0], %1;"
                     :: "r"(hdr), "r"(256u) : "memory");
        asm volatile("tcgen05.relinquish_alloc_permit.cta_group::1.sync.aligned;");
    }
    __syncthreads();
    uint32_t tmem;
    asm volatile("ld.shared.b32 %0, [%1];" : "=r"(tmem) : "r"(hdr));

    // prologue: fill 3 of 4 slots (steady state keeps 3 stages in flight)
#pragma unroll
    for (int s = 0; s < DEPTH - 1; s++) {
        load_stage(data_base, s, s, tok0, n0, tid);
        CP_COMMIT();
    }

    for (int ks = 0; ks < NKSTAGE; ks++) {
        const int slot = ks & (DEPTH - 1);
        CP_WAIT2();              // stage ks's fill complete (3 groups in flight)
        FENCE_ASYNC();
        __syncthreads();
        if (tid == 128) {
            uint64_t ad = make_desc(data_base + (uint32_t)slot * STAGE_BYTES);
            uint64_t bd = make_desc(data_base + (uint32_t)slot * STAGE_BYTES + B_OFF);
#pragma unroll
            for (int kk = 0; kk < 4; kk++)
                mma_f16_ss_cg1(tmem, ad + kk * 2, bd + kk * 2, MMA_IDESC,
                               (uint32_t)(ks | kk));
            TC_COMMIT(hdr + 8 + slot * 8);
        }
        // Refill stage ps = ks+3 into slot ps&3 == (ks-1)&3.
        // ks==0: slot 3 is virgin (no MMA has read it) -> no wait needed.
        // ks>=1: gate on commit of iteration ks-1 (already complete by now).
        const int ps = ks + DEPTH - 1;
        if (ps < NKSTAGE) {
            const int fslot = ps & (DEPTH - 1);
            if (ks >= 1)
                MBAR_WAIT(hdr + 8 + fslot * 8, (uint32_t)(((ks - 1) / DEPTH) & 1));
            load_stage(data_base, fslot, ps, tok0, n0, tid);
        }
        CP_COMMIT();  // exactly one group per iteration keeps wait_group<2> exact
    }

    if (tid == 128) TC_COMMIT(hdr + 8 + DEPTH * 8);
    MBAR_WAIT(hdr + 8 + DEPTH * 8, 0u);
    TC_FENCE_AFTER();

    // epilogue: warp w reads rows (w&3)*32+lane, cols (w>>2)*128 .. +127
    const int half = wid >> 2;
    const int mrow = (wid & 3) * 32 + lane;
    float runm = -1e30f, runs = 0.f;
#pragma unroll
    for (int cb = 0; cb < 4; cb++) {
        uint32_t r[32];
        TC_LD_X32(r, tmem + (uint32_t)(half * 128 + cb * 32));
        TC_WAIT_LD();
        float bm = -1e30f;
#pragma unroll
        for (int i = 0; i < 32; i++) bm = fmaxf(bm, __uint_as_float(r[i]));
        float nm = fmaxf(runm, bm);
        float sc = __expf(runm - nm);
        float bs = 0.f;
#pragma unroll
        for (int i = 0; i < 32; i++) bs += __expf(__uint_as_float(r[i]) - nm);
        runs = runs * sc + bs;
        runm = nm;
    }

    __syncthreads();  // MMAs + loads done; reuse stage smem for combine
    float* comb = reinterpret_cast<float*>(comb_c);
    comb[half * 128 + mrow] = runm;            // max[2][128]
    comb[256 + half * 128 + mrow] = runs;      // sum[2][128]
    __syncthreads();
    if (tid < 128) {
        float m0 = comb[tid], m1 = comb[128 + tid];
        float s0 = comb[256 + tid], s1 = comb[384 + tid];
        float m = fmaxf(m0, m1);
        float s = s0 * __expf(m0 - m) + s1 * __expf(m1 - m);
        g_pmax[blockIdx.y * TOKENS + tok0 + tid] = m;
        g_psum[blockIdx.y * TOKENS + tok0 + tid] = s;
    }
    __syncthreads();
    if (wid == 4) {
        asm volatile("tcgen05.dealloc.cta_group::1.sync.aligned.b32 %0, %1;"
                     :: "r"(tmem), "r"(256u));
    }
#endif  // HAS_TCGEN05
}

// =================== fallback path: mma.sync (always built) =================
__device__ __forceinline__ void mma16816(float* c, const uint32_t* a,
                                         uint32_t b0, uint32_t b1) {
    asm volatile(
        "mma.sync.aligned.m16n8k16.row.col.f32.bf16.bf16.f32 "
        "{%0,%1,%2,%3}, {%4,%5,%6,%7}, {%8,%9}, {%0,%1,%2,%3};\n"
        : "+f"(c[0]), "+f"(c[1]), "+f"(c[2]), "+f"(c[3])
        : "r"(a[0]), "r"(a[1]), "r"(a[2]), "r"(a[3]), "r"(b0), "r"(b1));
}

__global__ __launch_bounds__(256) void gemm_fb_kernel() {
    if (g_use_tc) return;
    __shared__ __nv_bfloat16 As[128][72];
    __shared__ __nv_bfloat16 Bs[128][72];

    const int tid  = threadIdx.x;
    const int tok0 = blockIdx.x * 128;
    const int n0g  = blockIdx.y * 128;
    const int wid  = tid >> 5, lane = tid & 31;
    const int wr   = wid >> 1, wc = wid & 1;
    const int g    = lane >> 2, tig = lane & 3;

    float acc[2][8][4];
#pragma unroll
    for (int mt = 0; mt < 2; mt++)
#pragma unroll
        for (int nt = 0; nt < 8; nt++)
#pragma unroll
            for (int i = 0; i < 4; i++) acc[mt][nt][i] = 0.f;

    for (int ko = 0; ko < DMODEL; ko += 64) {
#pragma unroll
        for (int j = 0; j < 4; j++) {
            int idx = tid + j * 256;
            int row = idx >> 3, kb = idx & 7;
            *(uint4*)&As[row][kb * 8] =
                *(const uint4*)&g_xb[(size_t)(tok0 + row) * DMODEL + ko + kb * 8];
            *(uint4*)&Bs[row][kb * 8] =
                *(const uint4*)&g_wb[(size_t)(n0g + row) * DMODEL + ko + kb * 8];
        }
        __syncthreads();
#pragma unroll
        for (int ks = 0; ks < 4; ks++) {
            const int k0 = ks * 16;
            uint32_t af[2][4];
#pragma unroll
            for (int mt = 0; mt < 2; mt++) {
                int r0 = wr * 32 + mt * 16 + g;
                af[mt][0] = *(const uint32_t*)&As[r0][k0 + tig * 2];
                af[mt][1] = *(const uint32_t*)&As[r0 + 8][k0 + tig * 2];
                af[mt][2] = *(const uint32_t*)&As[r0][k0 + 8 + tig * 2];
                af[mt][3] = *(const uint32_t*)&As[r0 + 8][k0 + 8 + tig * 2];
            }
#pragma unroll
            for (int nt = 0; nt < 8; nt++) {
                int nrow = wc * 64 + nt * 8 + g;
                uint32_t b0 = *(const uint32_t*)&Bs[nrow][k0 + tig * 2];
                uint32_t b1 = *(const uint32_t*)&Bs[nrow][k0 + 8 + tig * 2];
                mma16816(acc[0][nt], af[0], b0, b1);
                mma16816(acc[1][nt], af[1], b0, b1);
            }
        }
        __syncthreads();
    }

    const int chunk = blockIdx.y * 2 + wc;
#pragma unroll
    for (int mt = 0; mt < 2; mt++) {
        float mA = -1e30f, mB = -1e30f;
#pragma unroll
        for (int nt = 0; nt < 8; nt++) {
            mA = fmaxf(mA, fmaxf(acc[mt][nt][0], acc[mt][nt][1]));
            mB = fmaxf(mB, fmaxf(acc[mt][nt][2], acc[mt][nt][3]));
        }
        mA = fmaxf(mA, __shfl_xor_sync(0xffffffffu, mA, 1));
        mA = fmaxf(mA, __shfl_xor_sync(0xffffffffu, mA, 2));
        mB = fmaxf(mB, __shfl_xor_sync(0xffffffffu, mB, 1));
        mB = fmaxf(mB, __shfl_xor_sync(0xffffffffu, mB, 2));
        float sA = 0.f, sB = 0.f;
#pragma unroll
        for (int nt = 0; nt < 8; nt++) {
            sA += __expf(acc[mt][nt][0] - mA) + __expf(acc[mt][nt][1] - mA);
            sB += __expf(acc[mt][nt][2] - mB) + __expf(acc[mt][nt][3] - mB);
        }
        sA += __shfl_xor_sync(0xffffffffu, sA, 1);
        sA += __shfl_xor_sync(0xffffffffu, sA, 2);
        sB += __shfl_xor_sync(0xffffffffu, sB, 1);
        sB += __shfl_xor_sync(0xffffffffu, sB, 2);
        if (tig == 0) {
            int tA = tok0 + wr * 32 + mt * 16 + g;
            g_pmax[chunk * TOKENS + tA] = mA;
            g_psum[chunk * TOKENS + tA] = sA;
            g_pmax[chunk * TOKENS + tA + 8] = mB;
            g_psum[chunk * TOKENS + tA + 8] = sB;
        }
    }
}

// ----------------------- target score: x_t . W[target_t] --------------------
__global__ __launch_bounds__(256) void tscore_kernel(const float* __restrict__ x,
                                                     const float* __restrict__ w,
                                                     const int* __restrict__ target) {
    int wid = threadIdx.x >> 5, lane = threadIdx.x & 31;
    int t = blockIdx.x * 8 + wid;
    int tgt = target[t];
    const float4* xr = reinterpret_cast<const float4*>(x + (size_t)t * DMODEL);
    const float4* wrow = reinterpret_cast<const float4*>(w + (size_t)tgt * DMODEL);
    float s = 0.f;
#pragma unroll
    for (int i = 0; i < 8; i++) {
        float4 a = xr[lane + i * 32];
        float4 b = wrow[lane + i * 32];
        s += a.x * b.x + a.y * b.y + a.z * b.z + a.w * b.w;
    }
#pragma unroll
    for (int o = 16; o; o >>= 1) s += __shfl_xor_sync(0xffffffffu, s, o);
    if (lane == 0) g_tscore[t] = s;
}

// --------------------- per-token loss (parallel over SMs) -------------------
__global__ __launch_bounds__(128) void loss_kernel() {
    const int t = blockIdx.x * 128 + threadIdx.x;
    const int nch = g_use_tc ? NCHUNK_TC : NCHUNK_FB;
    float gm = -1e30f;
    for (int c = 0; c < nch; c++)
        gm = fmaxf(gm, g_pmax[c * TOKENS + t]);
    float s = 0.f;
    for (int c = 0; c < nch; c++)
        s += g_psum[c * TOKENS + t] * __expf(g_pmax[c * TOKENS + t] - gm);
    g_loss[t] = logf(s) + gm - g_tscore[t];
}

// ------------------------------ final scalar sum ----------------------------
__global__ void sum_kernel(float* __restrict__ out) {
    __shared__ double sred[1024];
    const int tid = threadIdx.x;
    double local = 0.0;
    for (int t = tid; t < TOKENS; t += 1024) local += (double)g_loss[t];
    sred[tid] = local;
    __syncthreads();
    for (int o = 512; o; o >>= 1) {
        if (tid < o) sred[tid] += sred[tid + o];
        __syncthreads();
    }
    if (tid == 0) out[0] = (float)sred[0];
}

// --------------------------------- launch -----------------------------------
extern "C" void kernel_launch(void* const* d_in, const int* in_sizes, int n_in,
                              void* d_out, int out_size) {
    const float* x = (const float*)d_in[0];
    const float* w = (const float*)d_in[1];
    const int* target = (const int*)d_in[2];
    float* out = (float*)d_out;
    (void)in_sizes; (void)n_in; (void)out_size;

    const int smem_bytes = DEPTH * STAGE_BYTES + 2048;
    cudaFuncSetAttribute(gemm_tc_kernel,
                         cudaFuncAttributeMaxDynamicSharedMemorySize, smem_bytes);

    __nv_bfloat16* xb;  cudaGetSymbolAddress((void**)&xb, g_xb);
    __nv_bfloat16* wb;  cudaGetSymbolAddress((void**)&wb, g_wb);

    flag_kernel<<<1, 1>>>();
    cvt_kernel<<<2048, 256>>>((const float4*)x, xb, TOKENS * DMODEL / 4);
    cvt_kernel<<<4096, 256>>>((const float4*)w, wb, VOCAB * DMODEL / 4);

    dim3 grid_tc(TOKENS / TILE_M, VOCAB / TILE_N);  // (64, 125)
    gemm_tc_kernel<<<grid_tc, 256, smem_bytes>>>();

    dim3 grid_fb(TOKENS / 128, VOCAB / 128);        // (64, 250)
    gemm_fb_kernel<<<grid_fb, 256>>>();

    tscore_kernel<<<TOKENS / 8, 256>>>(x, w, target);
    loss_kernel<<<TOKENS / 128, 128>>>();
    sum_kernel<<<1, 1024>>>(out);
}

// round 7
// speedup vs baseline: 5.5285x; 1.1741x over previous
#include <cuda_runtime.h>
#include <cuda_bf16.h>
#include <math.h>
#include <stdint.h>

#define TOKENS 8192
#define DMODEL 1024
#define VOCAB  32000
#define TILE_M 256
#define TILE_N 256
#define NCHUNK_TC (VOCAB / TILE_N)   // 125
#define NCHUNK_FB (VOCAB / 64)       // 500
#define KCHUNK 64
#define NKSTAGE (DMODEL / KCHUNK)    // 16
#define DEPTH 3
#define STAGE_BYTES 65536            // A0 16K + A1 16K + B 32K
#define A1_OFF 16384
#define B_OFF  32768

// idesc kind::f16: dtype F32(1<<4), atype BF16(1<<7), btype BF16(1<<10),
// N/8 << 17, M/16 << 24  ->  M=128 (per atom), N=256
#define MMA_IDESC 0x08400490u

#if defined(__CUDA_ARCH_FEAT_SM103_ALL) || defined(__CUDA_ARCH_FEAT_SM100_ALL)
#define HAS_TCGEN05 1
#else
#define HAS_TCGEN05 0
#endif

// -------- device scratch (allocation-free contract) -------------------------
__device__ __align__(16) __nv_bfloat16 g_xb[TOKENS * DMODEL];   // 16 MB
__device__ __align__(16) __nv_bfloat16 g_wb[VOCAB * DMODEL];    // 64 MB
__device__ float g_pmax[NCHUNK_FB * TOKENS];                    // sized for max
__device__ float g_psum[NCHUNK_FB * TOKENS];
__device__ float g_tscore[TOKENS];
__device__ float g_loss[TOKENS];
__device__ int   g_use_tc;

// ----------------------------- arch dispatch flag ---------------------------
__global__ void flag_kernel() {
#if HAS_TCGEN05
    g_use_tc = 1;
#else
    g_use_tc = 0;
#endif
}

// ---------------------------- fp32 -> bf16 convert --------------------------
__global__ void cvt_kernel(const float4* __restrict__ in,
                           __nv_bfloat16* __restrict__ outp, int n4) {
    uint2* out = reinterpret_cast<uint2*>(outp);
    int stride = gridDim.x * blockDim.x;
    for (int i = blockIdx.x * blockDim.x + threadIdx.x; i < n4; i += stride) {
        float4 v = in[i];
        __nv_bfloat162 a, b;
        a.x = __float2bfloat16(v.x); a.y = __float2bfloat16(v.y);
        b.x = __float2bfloat16(v.z); b.y = __float2bfloat16(v.w);
        uint2 o;
        o.x = *reinterpret_cast<unsigned int*>(&a);
        o.y = *reinterpret_cast<unsigned int*>(&b);
        out[i] = o;
    }
}

// ======================= tcgen05 path (feature-gated) =======================
#if HAS_TCGEN05
__device__ __forceinline__ uint32_t smem_u32(const void* p) {
    uint32_t a;
    asm("{ .reg .u64 t; cvta.to.shared.u64 t, %1; cvt.u32.u64 %0, t; }"
        : "=r"(a) : "l"(p));
    return a;
}
#define SW128(off) ((off) ^ (((off) >> 3) & 0x70))

static __device__ __forceinline__ uint64_t make_desc(uint32_t base) {
    // SW128 K-major: layout=2, version=1, SBO=64, LBO=1
    uint64_t d = ((uint64_t)2 << 61) | ((uint64_t)1 << 46) |
                 ((uint64_t)64 << 32) | ((uint64_t)1 << 16);
    return d | ((uint64_t)(base >> 4) & 0x3FFF);
}

__device__ __forceinline__ void mma_f16_ss_cg1(uint32_t d, uint64_t ad,
                                               uint64_t bd, uint32_t idesc,
                                               uint32_t en) {
    asm volatile(
        "{\n\t.reg .pred p;\n\t"
        "setp.ne.u32 p, %5, 0;\n\t"
        "tcgen05.mma.cta_group::1.kind::f16 [%0], %1, %2, %3, {%4,%4,%4,%4}, p;\n\t}"
        :: "r"(d), "l"(ad), "l"(bd), "r"(idesc), "r"(0u), "r"(en) : "memory");
}

#define MBAR_INIT(a, c) \
    asm volatile("mbarrier.init.shared.b64 [%0], %1;" :: "r"(a), "r"(c) : "memory")
#define TC_COMMIT(a) \
    asm volatile("tcgen05.commit.cta_group::1.mbarrier::arrive::one.shared::cluster.b64 [%0];" \
                 :: "r"(a) : "memory")
#define TC_FENCE_AFTER() asm volatile("tcgen05.fence::after_thread_sync;" ::: "memory")
#define FENCE_ASYNC() asm volatile("fence.proxy.async.shared::cta;" ::: "memory")
#define CP_COMMIT() asm volatile("cp.async.commit_group;" ::: "memory")
#define CP_WAIT1() asm volatile("cp.async.wait_group 1;" ::: "memory")

#define MBAR_WAIT(mbar, parity) do {                                          \
    uint32_t _m = (mbar); uint32_t _p = (parity); uint32_t _d;                \
    asm volatile("{\n\t.reg .pred p;\n\t"                                     \
        "mbarrier.try_wait.parity.acquire.cta.shared::cta.b64 p, [%1], %2;\n\t" \
        "selp.b32 %0, 1, 0, p;\n\t}"                                          \
        : "=r"(_d) : "r"(_m), "r"(_p) : "memory");                            \
    if (!_d) {                                                                \
        asm volatile("{\n\t.reg .pred P1;\n\t"                                \
            "W%=:\n\t"                                                        \
            "mbarrier.try_wait.parity.acquire.cta.shared::cta.b64 P1, [%0], %1, 0x989680;\n\t" \
            "@P1 bra.uni D%=;\n\t"                                            \
            "bra.uni W%=;\n\t"                                                \
            "D%=:\n\t}" :: "r"(_m), "r"(_p) : "memory");                      \
    }                                                                         \
} while (0)

#define TC_LD_X32(r, addr)                                                    \
    asm volatile("tcgen05.ld.sync.aligned.32x32b.x32.b32 "                    \
        "{%0,%1,%2,%3,%4,%5,%6,%7,%8,%9,%10,%11,%12,%13,%14,%15,"             \
        "%16,%17,%18,%19,%20,%21,%22,%23,%24,%25,%26,%27,%28,%29,%30,%31}, [%32];" \
        : "=r"((r)[0]), "=r"((r)[1]), "=r"((r)[2]), "=r"((r)[3]),             \
          "=r"((r)[4]), "=r"((r)[5]), "=r"((r)[6]), "=r"((r)[7]),             \
          "=r"((r)[8]), "=r"((r)[9]), "=r"((r)[10]), "=r"((r)[11]),           \
          "=r"((r)[12]), "=r"((r)[13]), "=r"((r)[14]), "=r"((r)[15]),         \
          "=r"((r)[16]), "=r"((r)[17]), "=r"((r)[18]), "=r"((r)[19]),         \
          "=r"((r)[20]), "=r"((r)[21]), "=r"((r)[22]), "=r"((r)[23]),         \
          "=r"((r)[24]), "=r"((r)[25]), "=r"((r)[26]), "=r"((r)[27]),         \
          "=r"((r)[28]), "=r"((r)[29]), "=r"((r)[30]), "=r"((r)[31])          \
        : "r"(addr))
#define TC_WAIT_LD() asm volatile("tcgen05.wait::ld.sync.aligned;" ::: "memory")

// Stage: A0 (tokens 0..127) 16KB | A1 (tokens 128..255) 16KB | B 32KB.
// 4096 16B chunks per stage -> 16 per thread.
__device__ __forceinline__ void load_stage(uint32_t data_base, int slot,
                                           int stage, int tok0, int n0, int tid) {
    const int ko = stage * KCHUNK;
    const uint32_t sbase = data_base + (uint32_t)slot * STAGE_BYTES;
#pragma unroll
    for (int j = 0; j < 16; j++) {
        int c = tid + j * 256;               // 0..4095
        int isB = c >= 2048;
        int cc = isB ? c - 2048 : c;
        int row = cc >> 3, c16 = cc & 7;     // A: row 0..255 ; B: row 0..255
        uint32_t dst;
        const __nv_bfloat16* src;
        if (isB) {
            uint32_t boff = (uint32_t)(row * 128 + c16 * 16);
            dst = sbase + B_OFF + SW128(boff);
            src = &g_wb[(size_t)(n0 + row) * DMODEL + ko + c16 * 8];
        } else {
            int half = row >> 7, r = row & 127;
            uint32_t boff = (uint32_t)(r * 128 + c16 * 16);
            dst = sbase + (half ? (uint32_t)A1_OFF : 0u) + SW128(boff);
            src = &g_xb[(size_t)(tok0 + row) * DMODEL + ko + c16 * 8];
        }
        asm volatile("cp.async.cg.shared.global [%0], [%1], 16;"
                     :: "r"(dst), "l"(src) : "memory");
    }
}
#endif  // HAS_TCGEN05

__global__ __launch_bounds__(256, 1) void gemm_tc_kernel() {
#if HAS_TCGEN05
    extern __shared__ char smem[];
    const uint32_t raw = smem_u32(smem);
    const uint32_t data_base = (raw + 1023u) & ~1023u;
    const uint32_t hdr = data_base + DEPTH * STAGE_BYTES;  // tmem ptr + barriers

    const int tid = threadIdx.x;
    const int wid = tid >> 5, lane = tid & 31;
    const int tok0 = blockIdx.x * TILE_M;
    const int n0 = blockIdx.y * TILE_N;

    if (tid == 0) {
#pragma unroll
        for (int b = 0; b < DEPTH; b++) MBAR_INIT(hdr + 8 + b * 8, 1u);
        MBAR_INIT(hdr + 8 + DEPTH * 8, 1u);   // done barrier
    }
    if (wid == 4) {
        asm volatile("tcgen05.alloc.cta_group::1.sync.aligned.shared::cta.b32 [%0], %1;"
                     :: "r"(hdr), "r"(512u) : "memory");
        asm volatile("tcgen05.relinquish_alloc_permit.cta_group::1.sync.aligned;");
    }
    __syncthreads();
    uint32_t tmem;
    asm volatile("ld.shared.b32 %0, [%1];" : "=r"(tmem) : "r"(hdr));

    // prologue: fill stages 0,1 (steady state keeps 2 stages in flight)
#pragma unroll
    for (int s = 0; s < DEPTH - 1; s++) {
        load_stage(data_base, s, s, tok0, n0, tid);
        CP_COMMIT();
    }

    for (int ks = 0; ks < NKSTAGE; ks++) {
        const int slot = ks % DEPTH;
        CP_WAIT1();              // stage ks's fill complete (2 groups in flight)
        FENCE_ASYNC();
        __syncthreads();
        if (tid == 128) {
            const uint32_t sb = data_base + (uint32_t)slot * STAGE_BYTES;
            uint64_t a0 = make_desc(sb);
            uint64_t a1 = make_desc(sb + A1_OFF);
            uint64_t bd = make_desc(sb + B_OFF);
#pragma unroll
            for (int kk = 0; kk < 4; kk++) {
                mma_f16_ss_cg1(tmem,        a0 + kk * 2, bd + kk * 2, MMA_IDESC,
                               (uint32_t)(ks | kk));
                mma_f16_ss_cg1(tmem + 256u, a1 + kk * 2, bd + kk * 2, MMA_IDESC,
                               (uint32_t)(ks | kk));
            }
            TC_COMMIT(hdr + 8 + slot * 8);
        }
        // Refill stage ps = ks+2 into slot ps%3 == (ks-1)%3.
        // ks==0: slot 2 virgin -> no wait. ks>=1: gate on commit of iter ks-1.
        const int ps = ks + DEPTH - 1;
        if (ps < NKSTAGE) {
            const int fslot = ps % DEPTH;
            if (ks >= 1)
                MBAR_WAIT(hdr + 8 + fslot * 8, (uint32_t)(((ks - 1) / DEPTH) & 1));
            load_stage(data_base, fslot, ps, tok0, n0, tid);
        }
        CP_COMMIT();  // exactly one group per iteration keeps wait_group<1> exact
    }

    if (tid == 128) TC_COMMIT(hdr + 8 + DEPTH * 8);
    MBAR_WAIT(hdr + 8 + DEPTH * 8, 0u);
    TC_FENCE_AFTER();

    // Epilogue: warp w owns tokens tok0 + (w>>2)*128 + (w&3)*32 + lane
    // (subpartition = w&3). D region (w>>2): cols (w>>2)*256 .. +255.
    const int half = wid >> 2;
    const int token = tok0 + half * 128 + (wid & 3) * 32 + lane;
    const uint32_t dbase = tmem + (uint32_t)(half * 256);
    float runm = -1e30f, runs = 0.f;
#pragma unroll
    for (int cb = 0; cb < 8; cb++) {
        uint32_t r[32];
        TC_LD_X32(r, dbase + (uint32_t)(cb * 32));
        TC_WAIT_LD();
        float bm = -1e30f;
#pragma unroll
        for (int i = 0; i < 32; i++) bm = fmaxf(bm, __uint_as_float(r[i]));
        float nm = fmaxf(runm, bm);
        float sc = __expf(runm - nm);
        float bs = 0.f;
#pragma unroll
        for (int i = 0; i < 32; i++) bs += __expf(__uint_as_float(r[i]) - nm);
        runs = runs * sc + bs;
        runm = nm;
    }
    g_pmax[blockIdx.y * TOKENS + token] = runm;
    g_psum[blockIdx.y * TOKENS + token] = runs;

    __syncthreads();
    if (wid == 4) {
        asm volatile("tcgen05.dealloc.cta_group::1.sync.aligned.b32 %0, %1;"
                     :: "r"(tmem), "r"(512u));
    }
#endif  // HAS_TCGEN05
}

// =================== fallback path: mma.sync (always built) =================
__device__ __forceinline__ void mma16816(float* c, const uint32_t* a,
                                         uint32_t b0, uint32_t b1) {
    asm volatile(
        "mma.sync.aligned.m16n8k16.row.col.f32.bf16.bf16.f32 "
        "{%0,%1,%2,%3}, {%4,%5,%6,%7}, {%8,%9}, {%0,%1,%2,%3};\n"
        : "+f"(c[0]), "+f"(c[1]), "+f"(c[2]), "+f"(c[3])
        : "r"(a[0]), "r"(a[1]), "r"(a[2]), "r"(a[3]), "r"(b0), "r"(b1));
}

__global__ __launch_bounds__(256) void gemm_fb_kernel() {
    if (g_use_tc) return;
    __shared__ __nv_bfloat16 As[128][72];
    __shared__ __nv_bfloat16 Bs[128][72];

    const int tid  = threadIdx.x;
    const int tok0 = blockIdx.x * 128;
    const int n0g  = blockIdx.y * 128;
    const int wid  = tid >> 5, lane = tid & 31;
    const int wr   = wid >> 1, wc = wid & 1;
    const int g    = lane >> 2, tig = lane & 3;

    float acc[2][8][4];
#pragma unroll
    for (int mt = 0; mt < 2; mt++)
#pragma unroll
        for (int nt = 0; nt < 8; nt++)
#pragma unroll
            for (int i = 0; i < 4; i++) acc[mt][nt][i] = 0.f;

    for (int ko = 0; ko < DMODEL; ko += 64) {
#pragma unroll
        for (int j = 0; j < 4; j++) {
            int idx = tid + j * 256;
            int row = idx >> 3, kb = idx & 7;
            *(uint4*)&As[row][kb * 8] =
                *(const uint4*)&g_xb[(size_t)(tok0 + row) * DMODEL + ko + kb * 8];
            *(uint4*)&Bs[row][kb * 8] =
                *(const uint4*)&g_wb[(size_t)(n0g + row) * DMODEL + ko + kb * 8];
        }
        __syncthreads();
#pragma unroll
        for (int ks = 0; ks < 4; ks++) {
            const int k0 = ks * 16;
            uint32_t af[2][4];
#pragma unroll
            for (int mt = 0; mt < 2; mt++) {
                int r0 = wr * 32 + mt * 16 + g;
                af[mt][0] = *(const uint32_t*)&As[r0][k0 + tig * 2];
                af[mt][1] = *(const uint32_t*)&As[r0 + 8][k0 + tig * 2];
                af[mt][2] = *(const uint32_t*)&As[r0][k0 + 8 + tig * 2];
                af[mt][3] = *(const uint32_t*)&As[r0 + 8][k0 + 8 + tig * 2];
            }
#pragma unroll
            for (int nt = 0; nt < 8; nt++) {
                int nrow = wc * 64 + nt * 8 + g;
                uint32_t b0 = *(const uint32_t*)&Bs[nrow][k0 + tig * 2];
                uint32_t b1 = *(const uint32_t*)&Bs[nrow][k0 + 8 + tig * 2];
                mma16816(acc[0][nt], af[0], b0, b1);
                mma16816(acc[1][nt], af[1], b0, b1);
            }
        }
        __syncthreads();
    }

    const int chunk = blockIdx.y * 2 + wc;
#pragma unroll
    for (int mt = 0; mt < 2; mt++) {
        float mA = -1e30f, mB = -1e30f;
#pragma unroll
        for (int nt = 0; nt < 8; nt++) {
            mA = fmaxf(mA, fmaxf(acc[mt][nt][0], acc[mt][nt][1]));
            mB = fmaxf(mB, fmaxf(acc[mt][nt][2], acc[mt][nt][3]));
        }
        mA = fmaxf(mA, __shfl_xor_sync(0xffffffffu, mA, 1));
        mA = fmaxf(mA, __shfl_xor_sync(0xffffffffu, mA, 2));
        mB = fmaxf(mB, __shfl_xor_sync(0xffffffffu, mB, 1));
        mB = fmaxf(mB, __shfl_xor_sync(0xffffffffu, mB, 2));
        float sA = 0.f, sB = 0.f;
#pragma unroll
        for (int nt = 0; nt < 8; nt++) {
            sA += __expf(acc[mt][nt][0] - mA) + __expf(acc[mt][nt][1] - mA);
            sB += __expf(acc[mt][nt][2] - mB) + __expf(acc[mt][nt][3] - mB);
        }
        sA += __shfl_xor_sync(0xffffffffu, sA, 1);
        sA += __shfl_xor_sync(0xffffffffu, sA, 2);
        sB += __shfl_xor_sync(0xffffffffu, sB, 1);
        sB += __shfl_xor_sync(0xffffffffu, sB, 2);
        if (tig == 0) {
            int tA = tok0 + wr * 32 + mt * 16 + g;
            g_pmax[chunk * TOKENS + tA] = mA;
            g_psum[chunk * TOKENS + tA] = sA;
            g_pmax[chunk * TOKENS + tA + 8] = mB;
            g_psum[chunk * TOKENS + tA + 8] = sB;
        }
    }
}

// ----------------------- target score: x_t . W[target_t] --------------------
__global__ __launch_bounds__(256) void tscore_kernel(const float* __restrict__ x,
                                                     const float* __restrict__ w,
                                                     const int* __restrict__ target) {
    int wid = threadIdx.x >> 5, lane = threadIdx.x & 31;
    int t = blockIdx.x * 8 + wid;
    int tgt = target[t];
    const float4* xr = reinterpret_cast<const float4*>(x + (size_t)t * DMODEL);
    const float4* wrow = reinterpret_cast<const float4*>(w + (size_t)tgt * DMODEL);
    float s = 0.f;
#pragma unroll
    for (int i = 0; i < 8; i++) {
        float4 a = xr[lane + i * 32];
        float4 b = wrow[lane + i * 32];
        s += a.x * b.x + a.y * b.y + a.z * b.z + a.w * b.w;
    }
#pragma unroll
    for (int o = 16; o; o >>= 1) s += __shfl_xor_sync(0xffffffffu, s, o);
    if (lane == 0) g_tscore[t] = s;
}

// --------------------- per-token loss (parallel over SMs) -------------------
__global__ __launch_bounds__(128) void loss_kernel() {
    const int t = blockIdx.x * 128 + threadIdx.x;
    const int nch = g_use_tc ? NCHUNK_TC : NCHUNK_FB;
    float gm = -1e30f;
    for (int c = 0; c < nch; c++)
        gm = fmaxf(gm, g_pmax[c * TOKENS + t]);
    float s = 0.f;
    for (int c = 0; c < nch; c++)
        s += g_psum[c * TOKENS + t] * __expf(g_pmax[c * TOKENS + t] - gm);
    g_loss[t] = logf(s) + gm - g_tscore[t];
}

// ------------------------------ final scalar sum ----------------------------
__global__ void sum_kernel(float* __restrict__ out) {
    __shared__ double sred[1024];
    const int tid = threadIdx.x;
    double local = 0.0;
    for (int t = tid; t < TOKENS; t += 1024) local += (double)g_loss[t];
    sred[tid] = local;
    __syncthreads();
    for (int o = 512; o; o >>= 1) {
        if (tid < o) sred[tid] += sred[tid + o];
        __syncthreads();
    }
    if (tid == 0) out[0] = (float)sred[0];
}

// --------------------------------- launch -----------------------------------
extern "C" void kernel_launch(void* const* d_in, const int* in_sizes, int n_in,
                              void* d_out, int out_size) {
    const float* x = (const float*)d_in[0];
    const float* w = (const float*)d_in[1];
    const int* target = (const int*)d_in[2];
    float* out = (float*)d_out;
    (void)in_sizes; (void)n_in; (void)out_size;

    const int smem_bytes = DEPTH * STAGE_BYTES + 2048;   // 198656
    cudaFuncSetAttribute(gemm_tc_kernel,
                         cudaFuncAttributeMaxDynamicSharedMemorySize, smem_bytes);

    __nv_bfloat16* xb;  cudaGetSymbolAddress((void**)&xb, g_xb);
    __nv_bfloat16* wb;  cudaGetSymbolAddress((void**)&wb, g_wb);

    flag_kernel<<<1, 1>>>();
    cvt_kernel<<<2048, 256>>>((const float4*)x, xb, TOKENS * DMODEL / 4);
    cvt_kernel<<<4096, 256>>>((const float4*)w, wb, VOCAB * DMODEL / 4);

    dim3 grid_tc(TOKENS / TILE_M, VOCAB / TILE_N);  // (32, 125) = 4000 CTAs
    gemm_tc_kernel<<<grid_tc, 256, smem_bytes>>>();

    dim3 grid_fb(TOKENS / 128, VOCAB / 128);        // (64, 250)
    gemm_fb_kernel<<<grid_fb, 256>>>();

    tscore_kernel<<<TOKENS / 8, 256>>>(x, w, target);
    loss_kernel<<<TOKENS / 128, 128>>>();
    sum_kernel<<<1, 1024>>>(out);
}

// round 8
// speedup vs baseline: 7.6735x; 1.3880x over previous
#include <cuda_runtime.h>
#include <cuda_bf16.h>
#include <cuda_fp8.h>
#include <math.h>
#include <stdint.h>

#define TOKENS 8192
#define DMODEL 1024
#define VOCAB  32000
#define TILE_M 256
#define TILE_N 248                     // 2 atoms x 248 D cols + 8 scale cols = 504 <= 512
#define NCHUNK_TC 130                  // ceil(32000 / 248)
#define KCHUNK 128                     // fp8 elements = bytes per SW128 row
#define NKSTAGE (DMODEL / KCHUNK)      // 8
#define DEPTH 3
#define A_BYTES (TILE_M * KCHUNK)      // 32768
#define B_BYTES (TILE_N * KCHUNK)      // 31744
#define B_OFF A_BYTES
#define STAGE_BYTES (A_BYTES + B_BYTES) // 64512 (1024-aligned)
#define SCALE_COL 496u                 // 8 cols of all-ones ue8m0, shared sfa/sfb
#define INV_SCALE 2.44140625e-4f       // 1/4096 (x,w pre-scaled by 64)

// idesc kind::mxf8f6f4: M=128 atom -> (128>>4)<<24, UE8M0 bit23, N/8 <<17, sf ids 0
#define MMA_IDESC ((8u << 24) | (1u << 23) | ((TILE_N / 8) << 17))

#if defined(__CUDA_ARCH_FEAT_SM103_ALL) || defined(__CUDA_ARCH_FEAT_SM100_ALL)
#define HAS_TCGEN05 1
#else
#define HAS_TCGEN05 0
#endif

// -------- device scratch (allocation-free contract) -------------------------
__device__ __align__(16) uint8_t g_xq[TOKENS * DMODEL];   // 8 MB e4m3 (x * 64)
__device__ __align__(16) uint8_t g_wq[VOCAB * DMODEL];    // 32 MB e4m3 (w * 64)
__device__ float g_pmax[NCHUNK_TC * TOKENS];
__device__ float g_psum[NCHUNK_TC * TOKENS];
__device__ float g_tscore[TOKENS];
__device__ float g_loss[TOKENS];

// ---------------------------- fp32 -> e4m3 (*64) ----------------------------
__global__ void cvt8_kernel(const float4* __restrict__ in,
                            uint8_t* __restrict__ outp, int n4) {
    uint32_t* out = reinterpret_cast<uint32_t*>(outp);
    int stride = gridDim.x * blockDim.x;
    for (int i = blockIdx.x * blockDim.x + threadIdx.x; i < n4; i += stride) {
        float4 v = in[i];
        __nv_fp8x2_storage_t lo = __nv_cvt_float2_to_fp8x2(
            make_float2(v.x * 64.f, v.y * 64.f), __NV_SATFINITE, __NV_E4M3);
        __nv_fp8x2_storage_t hi = __nv_cvt_float2_to_fp8x2(
            make_float2(v.z * 64.f, v.w * 64.f), __NV_SATFINITE, __NV_E4M3);
        out[i] = (uint32_t)lo | ((uint32_t)hi << 16);
    }
}

// ======================= tcgen05 path (feature-gated) =======================
#if HAS_TCGEN05
__device__ __forceinline__ uint32_t smem_u32(const void* p) {
    uint32_t a;
    asm("{ .reg .u64 t; cvta.to.shared.u64 t, %1; cvt.u32.u64 %0, t; }"
        : "=r"(a) : "l"(p));
    return a;
}
#define SW128(off) ((off) ^ (((off) >> 3) & 0x70))

static __device__ __forceinline__ uint64_t make_desc(uint32_t base) {
    // SW128 K-major: layout=2, version=1, SBO=64, LBO=1
    uint64_t d = ((uint64_t)2 << 61) | ((uint64_t)1 << 46) |
                 ((uint64_t)64 << 32) | ((uint64_t)1 << 16);
    return d | ((uint64_t)(base >> 4) & 0x3FFF);
}

__device__ __forceinline__ void mma_mxf8_ss(uint32_t d, uint64_t ad, uint64_t bd,
                                            uint32_t idesc, uint32_t sfa,
                                            uint32_t sfb, uint32_t en) {
    asm volatile(
        "{\n\t.reg .pred p;\n\t"
        "setp.ne.u32 p, %6, 0;\n\t"
        "tcgen05.mma.cta_group::1.kind::mxf8f6f4.block_scale.scale_vec::1X "
        "[%0], %1, %2, %3, [%4], [%5], p;\n\t}"
        :: "r"(d), "l"(ad), "l"(bd), "r"(idesc), "r"(sfa), "r"(sfb), "r"(en)
        : "memory");
}

#define MBAR_INIT(a, c) \
    asm volatile("mbarrier.init.shared.b64 [%0], %1;" :: "r"(a), "r"(c) : "memory")
#define TC_COMMIT(a) \
    asm volatile("tcgen05.commit.cta_group::1.mbarrier::arrive::one.shared::cluster.b64 [%0];" \
                 :: "r"(a) : "memory")
#define TC_FENCE_BEFORE() asm volatile("tcgen05.fence::before_thread_sync;" ::: "memory")
#define TC_FENCE_AFTER() asm volatile("tcgen05.fence::after_thread_sync;" ::: "memory")
#define FENCE_ASYNC() asm volatile("fence.proxy.async.shared::cta;" ::: "memory")
#define CP_COMMIT() asm volatile("cp.async.commit_group;" ::: "memory")
#define CP_WAIT1() asm volatile("cp.async.wait_group 1;" ::: "memory")

#define MBAR_WAIT(mbar, parity) do {                                          \
    uint32_t _m = (mbar); uint32_t _p = (parity); uint32_t _d;                \
    asm volatile("{\n\t.reg .pred p;\n\t"                                     \
        "mbarrier.try_wait.parity.acquire.cta.shared::cta.b64 p, [%1], %2;\n\t" \
        "selp.b32 %0, 1, 0, p;\n\t}"                                          \
        : "=r"(_d) : "r"(_m), "r"(_p) : "memory");                            \
    if (!_d) {                                                                \
        asm volatile("{\n\t.reg .pred P1;\n\t"                                \
            "W%=:\n\t"                                                        \
            "mbarrier.try_wait.parity.acquire.cta.shared::cta.b64 P1, [%0], %1, 0x989680;\n\t" \
            "@P1 bra.uni D%=;\n\t"                                            \
            "bra.uni W%=;\n\t"                                                \
            "D%=:\n\t}" :: "r"(_m), "r"(_p) : "memory");                      \
    }                                                                         \
} while (0)

#define TC_ST_X1(addr, v) \
    asm volatile("tcgen05.st.sync.aligned.32x32b.x1.b32 [%0], {%1};" \
                 :: "r"(addr), "r"(v) : "memory")
#define TC_WAIT_ST() asm volatile("tcgen05.wait::st.sync.aligned;" ::: "memory")

#define TC_LD_X32(r, addr)                                                    \
    asm volatile("tcgen05.ld.sync.aligned.32x32b.x32.b32 "                    \
        "{%0,%1,%2,%3,%4,%5,%6,%7,%8,%9,%10,%11,%12,%13,%14,%15,"             \
        "%16,%17,%18,%19,%20,%21,%22,%23,%24,%25,%26,%27,%28,%29,%30,%31}, [%32];" \
        : "=r"((r)[0]), "=r"((r)[1]), "=r"((r)[2]), "=r"((r)[3]),             \
          "=r"((r)[4]), "=r"((r)[5]), "=r"((r)[6]), "=r"((r)[7]),             \
          "=r"((r)[8]), "=r"((r)[9]), "=r"((r)[10]), "=r"((r)[11]),           \
          "=r"((r)[12]), "=r"((r)[13]), "=r"((r)[14]), "=r"((r)[15]),         \
          "=r"((r)[16]), "=r"((r)[17]), "=r"((r)[18]), "=r"((r)[19]),         \
          "=r"((r)[20]), "=r"((r)[21]), "=r"((r)[22]), "=r"((r)[23]),         \
          "=r"((r)[24]), "=r"((r)[25]), "=r"((r)[26]), "=r"((r)[27]),         \
          "=r"((r)[28]), "=r"((r)[29]), "=r"((r)[30]), "=r"((r)[31])          \
        : "r"(addr))
#define TC_WAIT_LD() asm volatile("tcgen05.wait::ld.sync.aligned;" ::: "memory")

// Stage: A 256 rows x 128B | B 248 rows x 128B. 4032 16B chunks, 256 threads.
__device__ __forceinline__ void load_stage(uint32_t data_base, int slot,
                                           int stage, int tok0, int n0, int tid) {
    const int ko = stage * KCHUNK;
    const uint32_t sbase = data_base + (uint32_t)slot * STAGE_BYTES;
#pragma unroll
    for (int j = 0; j < 16; j++) {
        int c = tid + j * 256;               // 0..4095, valid < 4032
        if (c < 2048) {                      // A
            int row = c >> 3, c16 = c & 7;
            uint32_t dst = sbase + SW128((uint32_t)(row * 128 + c16 * 16));
            const uint8_t* src = &g_xq[(size_t)(tok0 + row) * DMODEL + ko + c16 * 16];
            asm volatile("cp.async.cg.shared.global [%0], [%1], 16;"
                         :: "r"(dst), "l"(src) : "memory");
        } else if (c < 4032) {               // B (vocab rows, clamped for partial tile)
            int cc = c - 2048;
            int row = cc >> 3, c16 = cc & 7;
            uint32_t dst = sbase + B_OFF + SW128((uint32_t)(row * 128 + c16 * 16));
            int vr = n0 + row;
            if (vr > VOCAB - 1) vr = VOCAB - 1;
            const uint8_t* src = &g_wq[(size_t)vr * DMODEL + ko + c16 * 16];
            asm volatile("cp.async.cg.shared.global [%0], [%1], 16;"
                         :: "r"(dst), "l"(src) : "memory");
        }
    }
}
#endif  // HAS_TCGEN05

__global__ __launch_bounds__(256, 1) void gemm_tc_kernel() {
#if HAS_TCGEN05
    extern __shared__ char smem[];
    const uint32_t raw = smem_u32(smem);
    const uint32_t data_base = (raw + 1023u) & ~1023u;
    const uint32_t hdr = data_base + DEPTH * STAGE_BYTES;  // tmem ptr + barriers

    const int tid = threadIdx.x;
    const int wid = tid >> 5, lane = tid & 31;
    const int tok0 = blockIdx.x * TILE_M;
    const int n0 = blockIdx.y * TILE_N;

    if (tid == 0) {
#pragma unroll
        for (int b = 0; b < DEPTH; b++) MBAR_INIT(hdr + 8 + b * 8, 1u);
        MBAR_INIT(hdr + 8 + DEPTH * 8, 1u);   // done barrier
    }
    if (wid == 4) {
        asm volatile("tcgen05.alloc.cta_group::1.sync.aligned.shared::cta.b32 [%0], %1;"
                     :: "r"(hdr), "r"(512u) : "memory");
        asm volatile("tcgen05.relinquish_alloc_permit.cta_group::1.sync.aligned;");
    }
    __syncthreads();
    uint32_t tmem;
    asm volatile("ld.shared.b32 %0, [%1];" : "=r"(tmem) : "r"(hdr));

    // All-ones ue8m0 scales (exact no-op): 8 cols at SCALE_COL, every subpartition.
    if (wid < 4) {
        const uint32_t woff = ((uint32_t)wid) << 21;
#pragma unroll
        for (int c = 0; c < 8; c++)
            TC_ST_X1(tmem + SCALE_COL + (uint32_t)c + woff, 0x7F7F7F7Fu);
        TC_WAIT_ST();
        TC_FENCE_BEFORE();
    }
    __syncthreads();
    if (tid == 128) TC_FENCE_AFTER();

    // prologue: fill stages 0,1 (steady state keeps 2 stages in flight)
#pragma unroll
    for (int s = 0; s < DEPTH - 1; s++) {
        load_stage(data_base, s, s, tok0, n0, tid);
        CP_COMMIT();
    }

    for (int ks = 0; ks < NKSTAGE; ks++) {
        const int slot = ks % DEPTH;
        CP_WAIT1();              // stage ks's fill complete
        FENCE_ASYNC();
        __syncthreads();
        if (tid == 128) {
            const uint32_t sb = data_base + (uint32_t)slot * STAGE_BYTES;
            uint64_t ad = make_desc(sb);
            uint64_t bd = make_desc(sb + B_OFF);
            const uint32_t sf = tmem + SCALE_COL;
#pragma unroll
            for (int kk = 0; kk < 4; kk++) {   // K=32 per dispatch, 4 per stage
                mma_mxf8_ss(tmem,                 ad + kk * 2, bd + kk * 2,
                            MMA_IDESC, sf, sf, (uint32_t)(ks | kk));
                mma_mxf8_ss(tmem + (uint32_t)TILE_N,
                            make_desc(sb + A_BYTES / 2) + kk * 2, bd + kk * 2,
                            MMA_IDESC, sf, sf, (uint32_t)(ks | kk));
            }
            TC_COMMIT(hdr + 8 + slot * 8);
        }
        // Refill stage ps = ks+2 into slot ps%3 == (ks-1)%3.
        const int ps = ks + DEPTH - 1;
        if (ps < NKSTAGE) {
            const int fslot = ps % DEPTH;
            if (ks >= 1)
                MBAR_WAIT(hdr + 8 + fslot * 8, (uint32_t)(((ks - 1) / DEPTH) & 1));
            load_stage(data_base, fslot, ps, tok0, n0, tid);
        }
        CP_COMMIT();  // exactly one group per iteration keeps wait_group<1> exact
    }

    if (tid == 128) TC_COMMIT(hdr + 8 + DEPTH * 8);
    MBAR_WAIT(hdr + 8 + DEPTH * 8, 0u);
    TC_FENCE_AFTER();

    // Epilogue: warp w owns token tok0 + (w>>2)*128 + (w&3)*32 + lane.
    // D region (w>>2): cols (w>>2)*248 .. +247. Mask cols >= vlim with -1e30.
    const int half = wid >> 2;
    const int token = tok0 + half * 128 + (wid & 3) * 32 + lane;
    const uint32_t dbase = tmem + (uint32_t)(half * TILE_N);
    const int vlim = min(TILE_N, VOCAB - n0);
    float runm = -1e30f, runs = 0.f;
#pragma unroll
    for (int cb = 0; cb < 8; cb++) {
        uint32_t r[32];
        TC_LD_X32(r, dbase + (uint32_t)(cb * 32));
        TC_WAIT_LD();
        float v[32];
        float bm = -1e30f;
#pragma unroll
        for (int i = 0; i < 32; i++) {
            int j = cb * 32 + i;
            v[i] = (j < vlim) ? __uint_as_float(r[i]) * INV_SCALE : -1e30f;
            bm = fmaxf(bm, v[i]);
        }
        float nm = fmaxf(runm, bm);
        float sc = __expf(runm - nm);
        float bs = 0.f;
#pragma unroll
        for (int i = 0; i < 32; i++) bs += __expf(v[i] - nm);
        runs = runs * sc + bs;
        runm = nm;
    }
    g_pmax[blockIdx.y * TOKENS + token] = runm;
    g_psum[blockIdx.y * TOKENS + token] = runs;

    __syncthreads();
    if (wid == 4) {
        asm volatile("tcgen05.dealloc.cta_group::1.sync.aligned.b32 %0, %1;"
                     :: "r"(tmem), "r"(512u));
    }
#endif  // HAS_TCGEN05
}

// ----------------------- target score: x_t . W[target_t] --------------------
__global__ __launch_bounds__(256) void tscore_kernel(const float* __restrict__ x,
                                                     const float* __restrict__ w,
                                                     const int* __restrict__ target) {
    int wid = threadIdx.x >> 5, lane = threadIdx.x & 31;
    int t = blockIdx.x * 8 + wid;
    int tgt = target[t];
    const float4* xr = reinterpret_cast<const float4*>(x + (size_t)t * DMODEL);
    const float4* wrow = reinterpret_cast<const float4*>(w + (size_t)tgt * DMODEL);
    float s = 0.f;
#pragma unroll
    for (int i = 0; i < 8; i++) {
        float4 a = xr[lane + i * 32];
        float4 b = wrow[lane + i * 32];
        s += a.x * b.x + a.y * b.y + a.z * b.z + a.w * b.w;
    }
#pragma unroll
    for (int o = 16; o; o >>= 1) s += __shfl_xor_sync(0xffffffffu, s, o);
    if (lane == 0) g_tscore[t] = s;
}

// --------------------- per-token loss (parallel over SMs) -------------------
__global__ __launch_bounds__(128) void loss_kernel() {
    const int t = blockIdx.x * 128 + threadIdx.x;
    float gm = -1e30f;
    for (int c = 0; c < NCHUNK_TC; c++)
        gm = fmaxf(gm, g_pmax[c * TOKENS + t]);
    float s = 0.f;
    for (int c = 0; c < NCHUNK_TC; c++)
        s += g_psum[c * TOKENS + t] * __expf(g_pmax[c * TOKENS + t] - gm);
    g_loss[t] = logf(s) + gm - g_tscore[t];
}

// ------------------------------ final scalar sum ----------------------------
__global__ void sum_kernel(float* __restrict__ out) {
    __shared__ double sred[1024];
    const int tid = threadIdx.x;
    double local = 0.0;
    for (int t = tid; t < TOKENS; t += 1024) local += (double)g_loss[t];
    sred[tid] = local;
    __syncthreads();
    for (int o = 512; o; o >>= 1) {
        if (tid < o) sred[tid] += sred[tid + o];
        __syncthreads();
    }
    if (tid == 0) out[0] = (float)sred[0];
}

// --------------------------------- launch -----------------------------------
extern "C" void kernel_launch(void* const* d_in, const int* in_sizes, int n_in,
                              void* d_out, int out_size) {
    const float* x = (const float*)d_in[0];
    const float* w = (const float*)d_in[1];
    const int* target = (const int*)d_in[2];
    float* out = (float*)d_out;
    (void)in_sizes; (void)n_in; (void)out_size;

    const int smem_bytes = DEPTH * STAGE_BYTES + 1024;   // 194560
    cudaFuncSetAttribute(gemm_tc_kernel,
                         cudaFuncAttributeMaxDynamicSharedMemorySize, smem_bytes);

    uint8_t* xq;  cudaGetSymbolAddress((void**)&xq, g_xq);
    uint8_t* wq;  cudaGetSymbolAddress((void**)&wq, g_wq);

    cvt8_kernel<<<2048, 256>>>((const float4*)x, xq, TOKENS * DMODEL / 4);
    cvt8_kernel<<<4096, 256>>>((const float4*)w, wq, VOCAB * DMODEL / 4);

    dim3 grid_tc(TOKENS / TILE_M, NCHUNK_TC);  // (32, 130) = 4160 CTAs
    gemm_tc_kernel<<<grid_tc, 256, smem_bytes>>>();

    tscore_kernel<<<TOKENS / 8, 256>>>(x, w, target);
    loss_kernel<<<TOKENS / 128, 128>>>();
    sum_kernel<<<1, 1024>>>(out);
}

// round 9
// speedup vs baseline: 8.0221x; 1.0454x over previous
#include <cuda_runtime.h>
#include <cuda_bf16.h>
#include <cuda_fp8.h>
#include <math.h>
#include <stdint.h>

#define TOKENS 8192
#define DMODEL 1024
#define VOCAB  32000
#define TILE_M 256
#define TILE_N 248                     // 2 atoms x 248 D cols + 8 scale cols = 504 <= 512
#define NCHUNK_TC 130                  // ceil(32000 / 248)
#define NTILES (32 * NCHUNK_TC)        // 4160 tiles (32 token-tiles x 130 vocab-tiles)
#define GRID_TC 148                    // persistent: one wave (GB300 has 152 SMs)
#define KCHUNK 128                     // fp8 elements = bytes per SW128 row
#define DEPTH 3
#define A_BYTES (TILE_M * KCHUNK)      // 32768
#define B_BYTES (TILE_N * KCHUNK)      // 31744
#define B_OFF A_BYTES
#define STAGE_BYTES (A_BYTES + B_BYTES) // 64512 (1024-aligned)
#define SCALE_COL 496u                 // 8 cols of all-ones ue8m0, shared sfa/sfb
#define INV_SCALE 2.44140625e-4f       // 1/4096 (x,w pre-scaled by 64)

// idesc kind::mxf8f6f4: M=128 atom -> (128>>4)<<24, UE8M0 bit23, N/8 <<17, sf ids 0
#define MMA_IDESC ((8u << 24) | (1u << 23) | ((TILE_N / 8) << 17))

#if defined(__CUDA_ARCH_FEAT_SM103_ALL) || defined(__CUDA_ARCH_FEAT_SM100_ALL)
#define HAS_TCGEN05 1
#else
#define HAS_TCGEN05 0
#endif

// -------- device scratch (allocation-free contract) -------------------------
__device__ __align__(16) uint8_t g_xq[TOKENS * DMODEL];   // 8 MB e4m3 (x * 64)
__device__ __align__(16) uint8_t g_wq[VOCAB * DMODEL];    // 32 MB e4m3 (w * 64)
__device__ float g_pmax[NCHUNK_TC * TOKENS];
__device__ float g_psum[NCHUNK_TC * TOKENS];
__device__ float g_tscore[TOKENS];
__device__ float g_loss[TOKENS];

// ---------------------------- fp32 -> e4m3 (*64) ----------------------------
__global__ void cvt8_kernel(const float4* __restrict__ in,
                            uint8_t* __restrict__ outp, int n4) {
    uint32_t* out = reinterpret_cast<uint32_t*>(outp);
    int stride = gridDim.x * blockDim.x;
    for (int i = blockIdx.x * blockDim.x + threadIdx.x; i < n4; i += stride) {
        float4 v = in[i];
        __nv_fp8x2_storage_t lo = __nv_cvt_float2_to_fp8x2(
            make_float2(v.x * 64.f, v.y * 64.f), __NV_SATFINITE, __NV_E4M3);
        __nv_fp8x2_storage_t hi = __nv_cvt_float2_to_fp8x2(
            make_float2(v.z * 64.f, v.w * 64.f), __NV_SATFINITE, __NV_E4M3);
        out[i] = (uint32_t)lo | ((uint32_t)hi << 16);
    }
}

// ======================= tcgen05 path (feature-gated) =======================
#if HAS_TCGEN05
__device__ __forceinline__ uint32_t smem_u32(const void* p) {
    uint32_t a;
    asm("{ .reg .u64 t; cvta.to.shared.u64 t, %1; cvt.u32.u64 %0, t; }"
        : "=r"(a) : "l"(p));
    return a;
}
#define SW128(off) ((off) ^ (((off) >> 3) & 0x70))

static __device__ __forceinline__ uint64_t make_desc(uint32_t base) {
    // SW128 K-major: layout=2, version=1, SBO=64, LBO=1
    uint64_t d = ((uint64_t)2 << 61) | ((uint64_t)1 << 46) |
                 ((uint64_t)64 << 32) | ((uint64_t)1 << 16);
    return d | ((uint64_t)(base >> 4) & 0x3FFF);
}

__device__ __forceinline__ void mma_mxf8_ss(uint32_t d, uint64_t ad, uint64_t bd,
                                            uint32_t idesc, uint32_t sfa,
                                            uint32_t sfb, uint32_t en) {
    asm volatile(
        "{\n\t.reg .pred p;\n\t"
        "setp.ne.u32 p, %6, 0;\n\t"
        "tcgen05.mma.cta_group::1.kind::mxf8f6f4.block_scale.scale_vec::1X "
        "[%0], %1, %2, %3, [%4], [%5], p;\n\t}"
        :: "r"(d), "l"(ad), "l"(bd), "r"(idesc), "r"(sfa), "r"(sfb), "r"(en)
        : "memory");
}

#define MBAR_INIT(a, c) \
    asm volatile("mbarrier.init.shared.b64 [%0], %1;" :: "r"(a), "r"(c) : "memory")
#define TC_COMMIT(a) \
    asm volatile("tcgen05.commit.cta_group::1.mbarrier::arrive::one.shared::cluster.b64 [%0];" \
                 :: "r"(a) : "memory")
#define TC_FENCE_BEFORE() asm volatile("tcgen05.fence::before_thread_sync;" ::: "memory")
#define TC_FENCE_AFTER() asm volatile("tcgen05.fence::after_thread_sync;" ::: "memory")
#define FENCE_ASYNC() asm volatile("fence.proxy.async.shared::cta;" ::: "memory")
#define CP_COMMIT() asm volatile("cp.async.commit_group;" ::: "memory")
#define CP_WAIT1() asm volatile("cp.async.wait_group 1;" ::: "memory")

#define MBAR_WAIT(mbar, parity) do {                                          \
    uint32_t _m = (mbar); uint32_t _p = (parity); uint32_t _d;                \
    asm volatile("{\n\t.reg .pred p;\n\t"                                     \
        "mbarrier.try_wait.parity.acquire.cta.shared::cta.b64 p, [%1], %2;\n\t" \
        "selp.b32 %0, 1, 0, p;\n\t}"                                          \
        : "=r"(_d) : "r"(_m), "r"(_p) : "memory");                            \
    if (!_d) {                                                                \
        asm volatile("{\n\t.reg .pred P1;\n\t"                                \
            "W%=:\n\t"                                                        \
            "mbarrier.try_wait.parity.acquire.cta.shared::cta.b64 P1, [%0], %1, 0x989680;\n\t" \
            "@P1 bra.uni D%=;\n\t"                                            \
            "bra.uni W%=;\n\t"                                                \
            "D%=:\n\t}" :: "r"(_m), "r"(_p) : "memory");                      \
    }                                                                         \
} while (0)

#define TC_ST_X1(addr, v) \
    asm volatile("tcgen05.st.sync.aligned.32x32b.x1.b32 [%0], {%1};" \
                 :: "r"(addr), "r"(v) : "memory")
#define TC_WAIT_ST() asm volatile("tcgen05.wait::st.sync.aligned;" ::: "memory")

#define TC_LD_X32(r, addr)                                                    \
    asm volatile("tcgen05.ld.sync.aligned.32x32b.x32.b32 "                    \
        "{%0,%1,%2,%3,%4,%5,%6,%7,%8,%9,%10,%11,%12,%13,%14,%15,"             \
        "%16,%17,%18,%19,%20,%21,%22,%23,%24,%25,%26,%27,%28,%29,%30,%31}, [%32];" \
        : "=r"((r)[0]), "=r"((r)[1]), "=r"((r)[2]), "=r"((r)[3]),             \
          "=r"((r)[4]), "=r"((r)[5]), "=r"((r)[6]), "=r"((r)[7]),             \
          "=r"((r)[8]), "=r"((r)[9]), "=r"((r)[10]), "=r"((r)[11]),           \
          "=r"((r)[12]), "=r"((r)[13]), "=r"((r)[14]), "=r"((r)[15]),         \
          "=r"((r)[16]), "=r"((r)[17]), "=r"((r)[18]), "=r"((r)[19]),         \
          "=r"((r)[20]), "=r"((r)[21]), "=r"((r)[22]), "=r"((r)[23]),         \
          "=r"((r)[24]), "=r"((r)[25]), "=r"((r)[26]), "=r"((r)[27]),         \
          "=r"((r)[28]), "=r"((r)[29]), "=r"((r)[30]), "=r"((r)[31])          \
        : "r"(addr))
#define TC_WAIT_LD() asm volatile("tcgen05.wait::ld.sync.aligned;" ::: "memory")

// Stage: A 256 rows x 128B | B 248 rows x 128B. 4032 16B chunks, 256 threads.
__device__ __forceinline__ void load_stage(uint32_t data_base, int slot,
                                           int stage, int tok0, int n0, int tid) {
    const int ko = stage * KCHUNK;
    const uint32_t sbase = data_base + (uint32_t)slot * STAGE_BYTES;
#pragma unroll
    for (int j = 0; j < 16; j++) {
        int c = tid + j * 256;               // 0..4095, valid < 4032
        if (c < 2048) {                      // A
            int row = c >> 3, c16 = c & 7;
            uint32_t dst = sbase + SW128((uint32_t)(row * 128 + c16 * 16));
            const uint8_t* src = &g_xq[(size_t)(tok0 + row) * DMODEL + ko + c16 * 16];
            asm volatile("cp.async.cg.shared.global [%0], [%1], 16;"
                         :: "r"(dst), "l"(src) : "memory");
        } else if (c < 4032) {               // B (vocab rows, clamped for partial tile)
            int cc = c - 2048;
            int row = cc >> 3, c16 = cc & 7;
            uint32_t dst = sbase + B_OFF + SW128((uint32_t)(row * 128 + c16 * 16));
            int vr = n0 + row;
            if (vr > VOCAB - 1) vr = VOCAB - 1;
            const uint8_t* src = &g_wq[(size_t)vr * DMODEL + ko + c16 * 16];
            asm volatile("cp.async.cg.shared.global [%0], [%1], 16;"
                         :: "r"(dst), "l"(src) : "memory");
        }
    }
}
#endif  // HAS_TCGEN05

// Persistent: 148 CTAs loop over 4160 tiles (tile = bid + i*GRID_TC).
// tok0 = (tile % 32) * 256, vocab chunk = tile / 32. The cp.async ring is
// indexed by a flattened per-CTA global stage gsl = il*8 + ks and runs across
// tile boundaries, so next-tile loads overlap the current tile's epilogue.
__global__ __launch_bounds__(256, 1) void gemm_tc_kernel() {
#if HAS_TCGEN05
    extern __shared__ char smem[];
    const uint32_t raw = smem_u32(smem);
    const uint32_t data_base = (raw + 1023u) & ~1023u;
    const uint32_t hdr = data_base + DEPTH * STAGE_BYTES;  // tmem ptr + barriers

    const int tid = threadIdx.x;
    const int wid = tid >> 5, lane = tid & 31;
    const int bid = blockIdx.x;

    if (tid == 0) {
#pragma unroll
        for (int b = 0; b < DEPTH; b++) MBAR_INIT(hdr + 8 + b * 8, 1u);
        MBAR_INIT(hdr + 8 + DEPTH * 8, 1u);   // done barrier
    }
    if (wid == 4) {
        asm volatile("tcgen05.alloc.cta_group::1.sync.aligned.shared::cta.b32 [%0], %1;"
                     :: "r"(hdr), "r"(512u) : "memory");
        asm volatile("tcgen05.relinquish_alloc_permit.cta_group::1.sync.aligned;");
    }
    __syncthreads();
    uint32_t tmem;
    asm volatile("ld.shared.b32 %0, [%1];" : "=r"(tmem) : "r"(hdr));

    // All-ones ue8m0 scales (exact no-op): 8 cols at SCALE_COL, every subpartition.
    if (wid < 4) {
        const uint32_t woff = ((uint32_t)wid) << 21;
#pragma unroll
        for (int c = 0; c < 8; c++)
            TC_ST_X1(tmem + SCALE_COL + (uint32_t)c + woff, 0x7F7F7F7Fu);
        TC_WAIT_ST();
        TC_FENCE_BEFORE();
    }
    __syncthreads();

    const int ntl = (NTILES - bid + GRID_TC - 1) / GRID_TC;   // tiles for this CTA
    const int nstages = ntl * 8;

    // prologue: stages 0,1 (both belong to first tile)
    {
        const int t0 = bid;
        const int tok0 = (t0 & 31) << 8;
        const int n0 = (t0 >> 5) * TILE_N;
        load_stage(data_base, 0, 0, tok0, n0, tid);
        CP_COMMIT();
        load_stage(data_base, 1, 1, tok0, n0, tid);
        CP_COMMIT();
    }

    for (int il = 0; il < ntl; il++) {
        const int tile = bid + il * GRID_TC;
        const int n0 = (tile >> 5) * TILE_N;
        const int tok0 = (tile & 31) << 8;

        for (int ks = 0; ks < 8; ks++) {
            const int gsl = il * 8 + ks;
            const int slot = gsl % DEPTH;
            CP_WAIT1();              // stage gsl's fill complete
            FENCE_ASYNC();
            __syncthreads();
            if (tid == 128) {
                TC_FENCE_AFTER();
                const uint32_t sb = data_base + (uint32_t)slot * STAGE_BYTES;
                uint64_t ad = make_desc(sb);
                uint64_t a1 = make_desc(sb + A_BYTES / 2);
                uint64_t bd = make_desc(sb + B_OFF);
                const uint32_t sf = tmem + SCALE_COL;
#pragma unroll
                for (int kk = 0; kk < 4; kk++) {   // K=32 per dispatch
                    mma_mxf8_ss(tmem,                 ad + kk * 2, bd + kk * 2,
                                MMA_IDESC, sf, sf, (uint32_t)(ks | kk));
                    mma_mxf8_ss(tmem + (uint32_t)TILE_N, a1 + kk * 2, bd + kk * 2,
                                MMA_IDESC, sf, sf, (uint32_t)(ks | kk));
                }
                TC_COMMIT(hdr + 8 + slot * 8);
            }
            // Refill flattened stage ps = gsl+2 into slot ps%3 == (gsl-1)%3.
            // gsl==0: slot 2 virgin -> no wait. Else gate on commit of stage gsl-1.
            const int ps = gsl + 2;
            if (ps < nstages) {
                const int fslot = ps % DEPTH;
                if (gsl >= 1)
                    MBAR_WAIT(hdr + 8 + fslot * 8, (uint32_t)(((gsl - 1) / DEPTH) & 1));
                const int ptile = bid + (ps >> 3) * GRID_TC;
                load_stage(data_base, fslot, ps & 7,
                           (ptile & 31) << 8, (ptile >> 5) * TILE_N, tid);
            }
            CP_COMMIT();  // exactly one group per stage keeps wait_group<1> exact
        }

        if (tid == 128) TC_COMMIT(hdr + 8 + DEPTH * 8);
        MBAR_WAIT(hdr + 8 + DEPTH * 8, (uint32_t)(il & 1));
        TC_FENCE_AFTER();

        // Epilogue: warp w owns token tok0 + (w>>2)*128 + (w&3)*32 + lane.
        // D region (w>>2): cols (w>>2)*248 .. +247. Mask cols >= vlim.
        const int half = wid >> 2;
        const int token = tok0 + half * 128 + (wid & 3) * 32 + lane;
        const uint32_t dbase = tmem + (uint32_t)(half * TILE_N);
        const int vlim = min(TILE_N, VOCAB - n0);
        float runm = -1e30f, runs = 0.f;
#pragma unroll
        for (int cb = 0; cb < 8; cb++) {
            uint32_t r[32];
            TC_LD_X32(r, dbase + (uint32_t)(cb * 32));
            TC_WAIT_LD();
            float v[32];
            float bm = -1e30f;
#pragma unroll
            for (int i = 0; i < 32; i++) {
                int j = cb * 32 + i;
                v[i] = (j < vlim) ? __uint_as_float(r[i]) * INV_SCALE : -1e30f;
                bm = fmaxf(bm, v[i]);
            }
            float nm = fmaxf(runm, bm);
            float sc = __expf(runm - nm);
            float bs = 0.f;
#pragma unroll
            for (int i = 0; i < 32; i++) bs += __expf(v[i] - nm);
            runs = runs * sc + bs;
            runm = nm;
        }
        g_pmax[(tile >> 5) * TOKENS + token] = runm;
        g_psum[(tile >> 5) * TOKENS + token] = runs;

        TC_FENCE_BEFORE();
        __syncthreads();   // all epi TMEM reads done before next tile's MMA
    }

    if (wid == 4) {
        asm volatile("tcgen05.dealloc.cta_group::1.sync.aligned.b32 %0, %1;"
                     :: "r"(tmem), "r"(512u));
    }
#endif  // HAS_TCGEN05
}

// ----------------------- target score: x_t . W[target_t] --------------------
__global__ __launch_bounds__(256) void tscore_kernel(const float* __restrict__ x,
                                                     const float* __restrict__ w,
                                                     const int* __restrict__ target) {
    int wid = threadIdx.x >> 5, lane = threadIdx.x & 31;
    int t = blockIdx.x * 8 + wid;
    int tgt = target[t];
    const float4* xr = reinterpret_cast<const float4*>(x + (size_t)t * DMODEL);
    const float4* wrow = reinterpret_cast<const float4*>(w + (size_t)tgt * DMODEL);
    float s = 0.f;
#pragma unroll
    for (int i = 0; i < 8; i++) {
        float4 a = xr[lane + i * 32];
        float4 b = wrow[lane + i * 32];
        s += a.x * b.x + a.y * b.y + a.z * b.z + a.w * b.w;
    }
#pragma unroll
    for (int o = 16; o; o >>= 1) s += __shfl_xor_sync(0xffffffffu, s, o);
    if (lane == 0) g_tscore[t] = s;
}

// --------------------- per-token loss (parallel over SMs) -------------------
__global__ __launch_bounds__(128) void loss_kernel() {
    const int t = blockIdx.x * 128 + threadIdx.x;
    float gm = -1e30f;
    for (int c = 0; c < NCHUNK_TC; c++)
        gm = fmaxf(gm, g_pmax[c * TOKENS + t]);
    float s = 0.f;
    for (int c = 0; c < NCHUNK_TC; c++)
        s += g_psum[c * TOKENS + t] * __expf(g_pmax[c * TOKENS + t] - gm);
    g_loss[t] = logf(s) + gm - g_tscore[t];
}

// ------------------------------ final scalar sum ----------------------------
__global__ void sum_kernel(float* __restrict__ out) {
    __shared__ double sred[1024];
    const int tid = threadIdx.x;
    double local = 0.0;
    for (int t = tid; t < TOKENS; t += 1024) local += (double)g_loss[t];
    sred[tid] = local;
    __syncthreads();
    for (int o = 512; o; o >>= 1) {
        if (tid < o) sred[tid] += sred[tid + o];
        __syncthreads();
    }
    if (tid == 0) out[0] = (float)sred[0];
}

// --------------------------------- launch -----------------------------------
extern "C" void kernel_launch(void* const* d_in, const int* in_sizes, int n_in,
                              void* d_out, int out_size) {
    const float* x = (const float*)d_in[0];
    const float* w = (const float*)d_in[1];
    const int* target = (const int*)d_in[2];
    float* out = (float*)d_out;
    (void)in_sizes; (void)n_in; (void)out_size;

    const int smem_bytes = DEPTH * STAGE_BYTES + 1024;   // 194560
    cudaFuncSetAttribute(gemm_tc_kernel,
                         cudaFuncAttributeMaxDynamicSharedMemorySize, smem_bytes);

    uint8_t* xq;  cudaGetSymbolAddress((void**)&xq, g_xq);
    uint8_t* wq;  cudaGetSymbolAddress((void**)&wq, g_wq);

    cvt8_kernel<<<2048, 256>>>((const float4*)x, xq, TOKENS * DMODEL / 4);
    cvt8_kernel<<<4096, 256>>>((const float4*)w, wq, VOCAB * DMODEL / 4);

    gemm_tc_kernel<<<GRID_TC, 256, smem_bytes>>>();   // persistent, one wave

    tscore_kernel<<<TOKENS / 8, 256>>>(x, w, target);
    loss_kernel<<<TOKENS / 128, 128>>>();
    sum_kernel<<<1, 1024>>>(out);
}